// round 1
// baseline (speedup 1.0000x reference)
#include <cuda_runtime.h>

#define BB 4
#define NN 4096
#define KK 16
#define DM 128
#define DP 64
#define PTS (BB*NN)   // 16384

// ---------------- scratch (no allocations allowed) ----------------
__device__ int   g_knn[PTS*KK];     // 1 MB
__device__ float g_q [PTS*DM];      // 8 MB
__device__ float g_fk[PTS*DM];      // 8 MB
__device__ float g_fv[PTS*DM];      // 8 MB

// packed fp32x2 FMA (Blackwell): 2 fp32 FMAs per instruction
static __device__ __forceinline__ float2 ffma2(float2 a, float2 b, float2 c){
    float2 d;
    asm("fma.rn.f32x2 %0, %1, %2, %3;"
        : "=l"(reinterpret_cast<unsigned long long&>(d))
        : "l"(reinterpret_cast<unsigned long long&>(a)),
          "l"(reinterpret_cast<unsigned long long&>(b)),
          "l"(reinterpret_cast<unsigned long long&>(c)));
    return d;
}

// =================================================================
// Kernel 1: kNN.  grid (32, 4), 128 threads, 64KB smem.
// Maintains the 16 smallest (d, idx) lexicographically == top_k(-d2).
// =================================================================
__global__ void knn_kernel(const float* __restrict__ xyz)
{
    extern __shared__ float4 s4[];   // 4096 points: x,y,z,|x|^2
    int b  = blockIdx.y;
    int n0 = blockIdx.x * 128;
    const float* xb = xyz + (size_t)b*NN*3;
    for (int m = threadIdx.x; m < NN; m += 128){
        float x = xb[m*3+0], y = xb[m*3+1], z = xb[m*3+2];
        s4[m] = make_float4(x, y, z, x*x + y*y + z*z);
    }
    __syncthreads();

    int n = n0 + threadIdx.x;
    float4 qp = s4[n];
    float bd[KK]; int bi[KK];
    #pragma unroll
    for (int i = 0; i < KK; i++){ bd[i] = 3.4e38f; bi[i] = 0x7fffffff; }
    float worst = 3.4e38f; int wslot = 0;

    #pragma unroll 4
    for (int m = 0; m < NN; m++){
        float4 c = s4[m];
        float dot = qp.x*c.x + qp.y*c.y + qp.z*c.z;
        float d   = (qp.w + c.w) - 2.0f*dot;
        if (d < worst){                    // strict: ties keep incumbent (lower idx)
            bd[wslot] = d; bi[wslot] = m;
            float w = -3.4e38f; int wi = -1, ws = 0;
            #pragma unroll
            for (int i = 0; i < KK; i++){
                bool g = (bd[i] > w) || (bd[i] == w && bi[i] > wi);
                if (g){ w = bd[i]; wi = bi[i]; ws = i; }
            }
            worst = w; wslot = ws;
        }
    }
    int* outp = g_knn + ((size_t)b*NN + n)*KK;
    #pragma unroll
    for (int i = 0; i < KK; i++) outp[i] = bi[i];
}

// =================================================================
// Kernel 2: f = features@Wf1+bf1; q=f@Wq; fk=f@Wk; fv=f@Wv.
// (gather commutes with the linear maps, so these run at 16384 rows)
// grid 128, 256 threads, 160KB smem.
// =================================================================
__global__ void feat_kernel(const float* __restrict__ features,
                            const float* __restrict__ Wf1, const float* __restrict__ bf1,
                            const float* __restrict__ Wq,  const float* __restrict__ Wk,
                            const float* __restrict__ Wv)
{
    extern __shared__ float sm2[];
    float* sfeat = sm2;                 // 128*64
    float* sf    = sm2 + 128*64;        // 128*128
    float* sw    = sf  + 128*128;       // 128*128
    int tid  = threadIdx.x;
    int row0 = blockIdx.x * 128;

    for (int i = tid; i < 128*64/4; i += 256)
        ((float4*)sfeat)[i] = ((const float4*)(features + (size_t)row0*64))[i];
    for (int i = tid; i < 64*128/4; i += 256)
        ((float4*)sw)[i] = ((const float4*)Wf1)[i];
    __syncthreads();

    int dp = tid & 63;   // channel pair (2dp, 2dp+1)
    int rg = tid >> 6;   // 4 row groups of 32

    // f = features @ Wf1 + bf1   (K = 64)
    {
        float2 acc[32];
        float2 bias = *(const float2*)(bf1 + 2*dp);
        #pragma unroll
        for (int r = 0; r < 32; r++) acc[r] = bias;
        for (int j = 0; j < 64; j += 4){
            float2 w0 = *(float2*)(sw + (j+0)*128 + 2*dp);
            float2 w1 = *(float2*)(sw + (j+1)*128 + 2*dp);
            float2 w2 = *(float2*)(sw + (j+2)*128 + 2*dp);
            float2 w3 = *(float2*)(sw + (j+3)*128 + 2*dp);
            #pragma unroll
            for (int r = 0; r < 32; r++){
                float4 xv = *(float4*)(sfeat + (rg*32+r)*64 + j);
                acc[r] = ffma2(make_float2(xv.x,xv.x), w0, acc[r]);
                acc[r] = ffma2(make_float2(xv.y,xv.y), w1, acc[r]);
                acc[r] = ffma2(make_float2(xv.z,xv.z), w2, acc[r]);
                acc[r] = ffma2(make_float2(xv.w,xv.w), w3, acc[r]);
            }
        }
        #pragma unroll
        for (int r = 0; r < 32; r++)
            *(float2*)(sf + (rg*32+r)*128 + 2*dp) = acc[r];
    }
    __syncthreads();

    const float* Ws[3] = {Wq, Wk, Wv};
    for (int wsel = 0; wsel < 3; wsel++){
        for (int i = tid; i < 128*128/4; i += 256)
            ((float4*)sw)[i] = ((const float4*)Ws[wsel])[i];
        __syncthreads();
        float2 acc[32];
        #pragma unroll
        for (int r = 0; r < 32; r++) acc[r] = make_float2(0.f, 0.f);
        for (int j = 0; j < 128; j += 4){
            float2 w0 = *(float2*)(sw + (j+0)*128 + 2*dp);
            float2 w1 = *(float2*)(sw + (j+1)*128 + 2*dp);
            float2 w2 = *(float2*)(sw + (j+2)*128 + 2*dp);
            float2 w3 = *(float2*)(sw + (j+3)*128 + 2*dp);
            #pragma unroll
            for (int r = 0; r < 32; r++){
                float4 xv = *(float4*)(sf + (rg*32+r)*128 + j);
                acc[r] = ffma2(make_float2(xv.x,xv.x), w0, acc[r]);
                acc[r] = ffma2(make_float2(xv.y,xv.y), w1, acc[r]);
                acc[r] = ffma2(make_float2(xv.z,xv.z), w2, acc[r]);
                acc[r] = ffma2(make_float2(xv.w,xv.w), w3, acc[r]);
            }
        }
        float* gout = (wsel == 0) ? g_q : (wsel == 1) ? g_fk : g_fv;
        #pragma unroll
        for (int r = 0; r < 32; r++)
            *(float2*)(gout + (size_t)(row0 + rg*32 + r)*DM + 2*dp) = acc[r];
        __syncthreads();
    }
}

// =================================================================
// Kernel 3: fused per-point attention. Persistent: grid 148, 256 thr,
// 230KB smem; weights loaded once per block.
// =================================================================
__global__ void attn_kernel(const float* __restrict__ xyz, const float* __restrict__ features,
                            const float* __restrict__ Wd1, const float* __restrict__ bd1,
                            const float* __restrict__ Wd2, const float* __restrict__ bd2,
                            const float* __restrict__ Wg1, const float* __restrict__ bg1,
                            const float* __restrict__ Wg2, const float* __restrict__ bg2,
                            const float* __restrict__ Wo,  const float* __restrict__ bo,
                            float* __restrict__ out)
{
    extern __shared__ float sm3[];
    float* sWd2 = sm3;            // 16384
    float* sWg1 = sm3 + 16384;    // 16384
    float* sWg2 = sm3 + 32768;    // 16384
    float* bufA = sm3 + 49152;    // 4096: u/t pair-duplicated; later a (plain)
    float* bufC = sm3 + 53248;    // 2048: h (plain)
    float* bufB = sm3 + 55296;    // 2048: pos (plain)
    float* sq   = sm3 + 57344;    // 128
    float* sres = sm3 + 57472;    // 128
    int*   sidx = (int*)(sm3 + 57600); // 16
    float* sctr = sm3 + 57616;    // 4

    int tid = threadIdx.x;
    for (int i = tid; i < 16384/4; i += 256){
        ((float4*)sWd2)[i] = ((const float4*)Wd2)[i];
        ((float4*)sWg1)[i] = ((const float4*)Wg1)[i];
        ((float4*)sWg2)[i] = ((const float4*)Wg2)[i];
    }
    __syncthreads();

    int dp = tid & 63, rg = tid >> 6;
    const float invs = 0.08838834764831845f;   // 1/sqrt(128)

    int startP = (int)((long long)blockIdx.x     * PTS / gridDim.x);
    int endP   = (int)((long long)(blockIdx.x+1) * PTS / gridDim.x);

    for (int p = startP; p < endP; p++){
        int base = p & ~(NN-1);   // b*4096

        if (tid < 16)  sidx[tid] = g_knn[(size_t)p*KK + tid];
        if (tid < 128) sq[tid]   = g_q[(size_t)p*DM + tid];
        if (tid >= 128 && tid < 131) sctr[tid-128] = xyz[(size_t)p*3 + (tid-128)];
        __syncthreads();

        // ---- stage 1: u = relu(rel@Wd1 + bd1) -> bufA (pair-duplicated) ----
        {
            float2 bias = *(const float2*)(bd1 + 2*dp);
            float2 w0 = *(const float2*)(Wd1 + 0*128 + 2*dp);
            float2 w1 = *(const float2*)(Wd1 + 1*128 + 2*dp);
            float2 w2 = *(const float2*)(Wd1 + 2*128 + 2*dp);
            #pragma unroll
            for (int r = 0; r < 4; r++){
                int k  = rg*4 + r;
                int nb = base + sidx[k];
                float rx = sctr[0] - xyz[(size_t)nb*3+0];
                float ry = sctr[1] - xyz[(size_t)nb*3+1];
                float rz = sctr[2] - xyz[(size_t)nb*3+2];
                float2 acc = bias;
                acc = ffma2(make_float2(rx,rx), w0, acc);
                acc = ffma2(make_float2(ry,ry), w1, acc);
                acc = ffma2(make_float2(rz,rz), w2, acc);
                float ax = fmaxf(acc.x, 0.f), ay = fmaxf(acc.y, 0.f);
                *(float4*)(bufA + (k*128 + 2*dp)*2) = make_float4(ax, ax, ay, ay);
            }
        }
        __syncthreads();

        // ---- stage 2: pos = u@Wd2 + bd2 -> bufB (plain) ----
        {
            float2 acc[4];
            float2 bias = *(const float2*)(bd2 + 2*dp);
            #pragma unroll
            for (int r = 0; r < 4; r++) acc[r] = bias;
            for (int j = 0; j < 128; j += 2){
                float2 w0 = *(float2*)(sWd2 + (j+0)*128 + 2*dp);
                float2 w1 = *(float2*)(sWd2 + (j+1)*128 + 2*dp);
                #pragma unroll
                for (int r = 0; r < 4; r++){
                    float4 xv = *(float4*)(bufA + ((rg*4+r)*128 + j)*2);
                    acc[r] = ffma2(make_float2(xv.x,xv.y), w0, acc[r]);
                    acc[r] = ffma2(make_float2(xv.z,xv.w), w1, acc[r]);
                }
            }
            #pragma unroll
            for (int r = 0; r < 4; r++)
                *(float2*)(bufB + (rg*4+r)*128 + 2*dp) = acc[r];
        }
        __syncthreads();

        // ---- stage 3: t = q - fk[knn] + pos -> bufA (pair-duplicated) ----
        {
            float2 qv = *(float2*)(sq + 2*dp);
            #pragma unroll
            for (int r = 0; r < 4; r++){
                int k  = rg*4 + r;
                int nb = base + sidx[k];
                float2 kv = *(const float2*)(g_fk + (size_t)nb*DM + 2*dp);
                float2 pv = *(float2*)(bufB + k*128 + 2*dp);
                float tx = qv.x - kv.x + pv.x;
                float ty = qv.y - kv.y + pv.y;
                *(float4*)(bufA + (k*128 + 2*dp)*2) = make_float4(tx, tx, ty, ty);
            }
        }
        __syncthreads();

        // ---- stage 4: h = relu(t@Wg1 + bg1) -> bufC (plain) ----
        {
            float2 acc[4];
            float2 bias = *(const float2*)(bg1 + 2*dp);
            #pragma unroll
            for (int r = 0; r < 4; r++) acc[r] = bias;
            for (int j = 0; j < 128; j += 2){
                float2 w0 = *(float2*)(sWg1 + (j+0)*128 + 2*dp);
                float2 w1 = *(float2*)(sWg1 + (j+1)*128 + 2*dp);
                #pragma unroll
                for (int r = 0; r < 4; r++){
                    float4 xv = *(float4*)(bufA + ((rg*4+r)*128 + j)*2);
                    acc[r] = ffma2(make_float2(xv.x,xv.y), w0, acc[r]);
                    acc[r] = ffma2(make_float2(xv.z,xv.w), w1, acc[r]);
                }
            }
            #pragma unroll
            for (int r = 0; r < 4; r++){
                float2 a = acc[r];
                a.x = fmaxf(a.x, 0.f); a.y = fmaxf(a.y, 0.f);
                *(float2*)(bufC + (rg*4+r)*128 + 2*dp) = a;
            }
        }
        __syncthreads();

        // ---- stage 5: a = h@Wg2 + bg2 -> bufA (plain, overwrites t) ----
        {
            float2 acc[4];
            float2 bias = *(const float2*)(bg2 + 2*dp);
            #pragma unroll
            for (int r = 0; r < 4; r++) acc[r] = bias;
            for (int j = 0; j < 128; j += 4){
                float2 w0 = *(float2*)(sWg2 + (j+0)*128 + 2*dp);
                float2 w1 = *(float2*)(sWg2 + (j+1)*128 + 2*dp);
                float2 w2 = *(float2*)(sWg2 + (j+2)*128 + 2*dp);
                float2 w3 = *(float2*)(sWg2 + (j+3)*128 + 2*dp);
                #pragma unroll
                for (int r = 0; r < 4; r++){
                    float4 xv = *(float4*)(bufC + (rg*4+r)*128 + j);
                    acc[r] = ffma2(make_float2(xv.x,xv.x), w0, acc[r]);
                    acc[r] = ffma2(make_float2(xv.y,xv.y), w1, acc[r]);
                    acc[r] = ffma2(make_float2(xv.z,xv.z), w2, acc[r]);
                    acc[r] = ffma2(make_float2(xv.w,xv.w), w3, acc[r]);
                }
            }
            __syncthreads();   // bufA (t) dead only after all GEMM reads done
            #pragma unroll
            for (int r = 0; r < 4; r++)
                *(float2*)(bufA + (rg*4+r)*128 + 2*dp) = acc[r];
        }
        __syncthreads();

        // ---- stage 6: softmax over k per channel; res = sum attn*(v+pos) ----
        if (tid < 128){
            int d = tid;
            float y[KK];
            float mx = -3.4e38f;
            #pragma unroll
            for (int k = 0; k < KK; k++){
                y[k] = bufA[k*128 + d] * invs;
                mx = fmaxf(mx, y[k]);
            }
            float s = 0.f;
            #pragma unroll
            for (int k = 0; k < KK; k++){ y[k] = __expf(y[k] - mx); s += y[k]; }
            float inv_s = 1.f / s;
            float res = 0.f;
            #pragma unroll
            for (int k = 0; k < KK; k++){
                int nb = base + sidx[k];
                float w = g_fv[(size_t)nb*DM + d] + bufB[k*128 + d];
                res += y[k] * w;
            }
            sres[d] = res * inv_s;
        }
        __syncthreads();

        // ---- stage 7: out = res@Wo + bo + shortcut ----
        if (tid < 64){
            int o = tid;
            float acc = bo[o];
            #pragma unroll 16
            for (int d = 0; d < 128; d++)
                acc = fmaf(sres[d], Wo[d*DP + o], acc);
            out[(size_t)p*DP + o] = acc + features[(size_t)p*DP + o];
        }
        __syncthreads();
    }
}

// =================================================================
extern "C" void kernel_launch(void* const* d_in, const int* in_sizes, int n_in,
                              void* d_out, int out_size)
{
    const float* xyz      = (const float*)d_in[0];
    const float* features = (const float*)d_in[1];
    const float* Wd1 = (const float*)d_in[2];  const float* bd1 = (const float*)d_in[3];
    const float* Wd2 = (const float*)d_in[4];  const float* bd2 = (const float*)d_in[5];
    const float* Wf1 = (const float*)d_in[6];  const float* bf1 = (const float*)d_in[7];
    const float* Wq  = (const float*)d_in[8];
    const float* Wk  = (const float*)d_in[9];
    const float* Wv  = (const float*)d_in[10];
    const float* Wg1 = (const float*)d_in[11]; const float* bg1 = (const float*)d_in[12];
    const float* Wg2 = (const float*)d_in[13]; const float* bg2 = (const float*)d_in[14];
    const float* Wo  = (const float*)d_in[15]; const float* bo  = (const float*)d_in[16];
    float* out = (float*)d_out;

    cudaFuncSetAttribute(knn_kernel,  cudaFuncAttributeMaxDynamicSharedMemorySize, 65536);
    cudaFuncSetAttribute(feat_kernel, cudaFuncAttributeMaxDynamicSharedMemorySize, 163840);
    cudaFuncSetAttribute(attn_kernel, cudaFuncAttributeMaxDynamicSharedMemorySize, 230528);

    knn_kernel <<<dim3(32, 4), 128, 65536 >>>(xyz);
    feat_kernel<<<128, 256, 163840>>>(features, Wf1, bf1, Wq, Wk, Wv);
    attn_kernel<<<148, 256, 230528>>>(xyz, features, Wd1, bd1, Wd2, bd2,
                                      Wg1, bg1, Wg2, bg2, Wo, bo, out);
}

// round 2
// speedup vs baseline: 1.6176x; 1.6176x over previous
#include <cuda_runtime.h>

#define BB 4
#define NN 4096
#define KK 16
#define DM 128
#define DP 64
#define PTS (BB*NN)      // 16384
#define TILE_P 4         // points per tile in pos/attn kernels (64 rows)

// ---------------- scratch (no allocations allowed) ----------------
__device__ int   g_knn[PTS*KK];          // 1 MB
__device__ float g_q  [PTS*DM];          // 8 MB
__device__ float g_fk [PTS*DM];          // 8 MB
__device__ float g_fv [PTS*DM];          // 8 MB
__device__ float g_pos[(size_t)PTS*KK*DM]; // 128 MB
__device__ float g_res[PTS*DM];          // 8 MB

// packed fp32x2 FMA (Blackwell): 2 fp32 FMAs per instruction
static __device__ __forceinline__ float2 ffma2(float2 a, float2 b, float2 c){
    float2 d;
    asm("fma.rn.f32x2 %0, %1, %2, %3;"
        : "=l"(reinterpret_cast<unsigned long long&>(d))
        : "l"(reinterpret_cast<unsigned long long&>(a)),
          "l"(reinterpret_cast<unsigned long long&>(b)),
          "l"(reinterpret_cast<unsigned long long&>(c)));
    return d;
}

// =================================================================
// Kernel 1: kNN. 8 queries/warp, 4 lanes/query. Register-resident
// sorted top-16 per lane (branchless insertion chain), quad merge.
// grid (64, 4), 256 threads, 64KB smem.
// =================================================================
__global__ void __launch_bounds__(256, 3) knn_kernel(const float* __restrict__ xyz)
{
    extern __shared__ float4 s4[];   // 4096 points: x,y,z,|x|^2
    int b = blockIdx.y;
    const float* xb = xyz + (size_t)b*NN*3;
    for (int m = threadIdx.x; m < NN; m += blockDim.x){
        float x = xb[m*3+0], y = xb[m*3+1], z = xb[m*3+2];
        s4[m] = make_float4(x, y, z, x*x + y*y + z*z);
    }
    __syncthreads();

    int lane = threadIdx.x & 31;
    int warp = threadIdx.x >> 5;          // 8 warps
    int quad = lane >> 2;                 // query within warp (0..7)
    int sl   = lane & 3;                  // candidate stripe (0..3)
    int q    = blockIdx.x*64 + warp*8 + quad;

    float4 qp = s4[q];
    float bd[KK]; int bi[KK];
    #pragma unroll
    for (int i = 0; i < KK; i++){ bd[i] = 3.4e38f; bi[i] = 0x7fffffff; }

    #pragma unroll 4
    for (int t = 0; t < NN/4; t++){
        int m = sl + 4*t;
        float4 c = s4[m];
        float d = qp.w + c.w;
        d = fmaf(-2.0f*c.x, qp.x, d);
        d = fmaf(-2.0f*c.y, qp.y, d);
        d = fmaf(-2.0f*c.z, qp.z, d);
        if (d < bd[KK-1]){
            float cd = d; int ci = m;
            #pragma unroll
            for (int i = 0; i < KK; i++){
                bool less = cd < bd[i];
                float nd = less ? cd : bd[i];
                int   ni = less ? ci : bi[i];
                float xd = less ? bd[i] : cd;
                int   xi = less ? bi[i] : ci;
                bd[i] = nd; bi[i] = ni; cd = xd; ci = xi;
            }
        }
    }

    // merge the 4 stripes of each quad: 16 rounds of extract-min
    int* outp = g_knn + ((size_t)b*NN + q)*KK;
    #pragma unroll 1
    for (int r = 0; r < KK; r++){
        float md = bd[0]; int mi = bi[0];
        float od; int oi;
        od = __shfl_xor_sync(0xffffffffu, md, 1); oi = __shfl_xor_sync(0xffffffffu, mi, 1);
        if (od < md || (od == md && oi < mi)){ md = od; mi = oi; }
        od = __shfl_xor_sync(0xffffffffu, md, 2); oi = __shfl_xor_sync(0xffffffffu, mi, 2);
        if (od < md || (od == md && oi < mi)){ md = od; mi = oi; }
        if (mi == bi[0] && md == bd[0]){   // this lane won: pop head
            #pragma unroll
            for (int i = 0; i < KK-1; i++){ bd[i] = bd[i+1]; bi[i] = bi[i+1]; }
            bd[KK-1] = 3.4e38f; bi[KK-1] = 0x7fffffff;
        }
        if (sl == 0) outp[r] = mi;
    }
}

// =================================================================
// Kernel 2: f = features@Wf1+bf1; q=f@Wq; fk=f@Wk; fv=f@Wv.
// (gather commutes with the linear maps -> run at 16384 rows)
// =================================================================
__global__ void __launch_bounds__(256, 1) feat_kernel(
    const float* __restrict__ features,
    const float* __restrict__ Wf1, const float* __restrict__ bf1,
    const float* __restrict__ Wq,  const float* __restrict__ Wk,
    const float* __restrict__ Wv)
{
    extern __shared__ float sm2[];
    float* sfeat = sm2;                 // 128*64
    float* sf    = sm2 + 128*64;        // 128*128
    float* sw    = sf  + 128*128;       // 128*128
    int tid  = threadIdx.x;
    int row0 = blockIdx.x * 128;

    for (int i = tid; i < 128*64/4; i += 256)
        ((float4*)sfeat)[i] = ((const float4*)(features + (size_t)row0*64))[i];
    for (int i = tid; i < 64*128/4; i += 256)
        ((float4*)sw)[i] = ((const float4*)Wf1)[i];
    __syncthreads();

    int dp = tid & 63;
    int rg = tid >> 6;

    {
        float2 acc[32];
        float2 bias = *(const float2*)(bf1 + 2*dp);
        #pragma unroll
        for (int r = 0; r < 32; r++) acc[r] = bias;
        for (int j = 0; j < 64; j += 4){
            float2 w0 = *(float2*)(sw + (j+0)*128 + 2*dp);
            float2 w1 = *(float2*)(sw + (j+1)*128 + 2*dp);
            float2 w2 = *(float2*)(sw + (j+2)*128 + 2*dp);
            float2 w3 = *(float2*)(sw + (j+3)*128 + 2*dp);
            #pragma unroll
            for (int r = 0; r < 32; r++){
                float4 xv = *(float4*)(sfeat + (rg*32+r)*64 + j);
                acc[r] = ffma2(make_float2(xv.x,xv.x), w0, acc[r]);
                acc[r] = ffma2(make_float2(xv.y,xv.y), w1, acc[r]);
                acc[r] = ffma2(make_float2(xv.z,xv.z), w2, acc[r]);
                acc[r] = ffma2(make_float2(xv.w,xv.w), w3, acc[r]);
            }
        }
        #pragma unroll
        for (int r = 0; r < 32; r++)
            *(float2*)(sf + (rg*32+r)*128 + 2*dp) = acc[r];
    }
    __syncthreads();

    const float* Ws[3] = {Wq, Wk, Wv};
    for (int wsel = 0; wsel < 3; wsel++){
        for (int i = tid; i < 128*128/4; i += 256)
            ((float4*)sw)[i] = ((const float4*)Ws[wsel])[i];
        __syncthreads();
        float2 acc[32];
        #pragma unroll
        for (int r = 0; r < 32; r++) acc[r] = make_float2(0.f, 0.f);
        for (int j = 0; j < 128; j += 4){
            float2 w0 = *(float2*)(sw + (j+0)*128 + 2*dp);
            float2 w1 = *(float2*)(sw + (j+1)*128 + 2*dp);
            float2 w2 = *(float2*)(sw + (j+2)*128 + 2*dp);
            float2 w3 = *(float2*)(sw + (j+3)*128 + 2*dp);
            #pragma unroll
            for (int r = 0; r < 32; r++){
                float4 xv = *(float4*)(sf + (rg*32+r)*128 + j);
                acc[r] = ffma2(make_float2(xv.x,xv.x), w0, acc[r]);
                acc[r] = ffma2(make_float2(xv.y,xv.y), w1, acc[r]);
                acc[r] = ffma2(make_float2(xv.z,xv.z), w2, acc[r]);
                acc[r] = ffma2(make_float2(xv.w,xv.w), w3, acc[r]);
            }
        }
        float* gout = (wsel == 0) ? g_q : (wsel == 1) ? g_fk : g_fv;
        #pragma unroll
        for (int r = 0; r < 32; r++)
            *(float2*)(gout + (size_t)(row0 + rg*32 + r)*DM + 2*dp) = acc[r];
        __syncthreads();
    }
}

// =================================================================
// Kernel 3: pos = relu(rel@Wd1+bd1)@Wd2+bd2 for all (p,k) rows.
// 64-row tiles (4 points), grid 4096, Wd2 in smem, u pair-duplicated.
// =================================================================
__global__ void __launch_bounds__(256, 1) pos_kernel(
    const float* __restrict__ xyz,
    const float* __restrict__ Wd1, const float* __restrict__ bd1,
    const float* __restrict__ Wd2, const float* __restrict__ bd2)
{
    extern __shared__ float smC[];
    float* sW   = smC;               // 16384 floats
    float* bufU = smC + 16384;       // 16384 floats (64 rows, dup)
    int*   sidx = (int*)(smC + 32768);  // 64
    float* sctr = smC + 32768 + 64;     // 12

    int tid = threadIdx.x;
    int p0  = blockIdx.x * TILE_P;
    int base = p0 & ~(NN-1);

    for (int i = tid; i < 16384/4; i += 256)
        ((float4*)sW)[i] = ((const float4*)Wd2)[i];
    if (tid < 64) sidx[tid] = g_knn[(size_t)p0*KK + tid];
    if (tid < 12) sctr[tid] = xyz[(size_t)p0*3 + tid];
    __syncthreads();

    int dp = tid & 63, rg = tid >> 6;   // rg = point within tile

    // stage 1: u = relu(rel@Wd1 + bd1), pair-duplicated
    {
        float2 bias = *(const float2*)(bd1 + 2*dp);
        float2 w0 = *(const float2*)(Wd1 +   0 + 2*dp);
        float2 w1 = *(const float2*)(Wd1 + 128 + 2*dp);
        float2 w2 = *(const float2*)(Wd1 + 256 + 2*dp);
        float cx = sctr[rg*3+0], cy = sctr[rg*3+1], cz = sctr[rg*3+2];
        #pragma unroll
        for (int r = 0; r < KK; r++){
            int nb = base + sidx[rg*KK + r];
            float rx = cx - xyz[(size_t)nb*3+0];
            float ry = cy - xyz[(size_t)nb*3+1];
            float rz = cz - xyz[(size_t)nb*3+2];
            float2 acc = bias;
            acc = ffma2(make_float2(rx,rx), w0, acc);
            acc = ffma2(make_float2(ry,ry), w1, acc);
            acc = ffma2(make_float2(rz,rz), w2, acc);
            float ax = fmaxf(acc.x, 0.f), ay = fmaxf(acc.y, 0.f);
            *(float4*)(bufU + ((rg*KK+r)*128 + 2*dp)*2) = make_float4(ax, ax, ay, ay);
        }
    }
    __syncthreads();

    // stage 2: pos = u@Wd2 + bd2 -> global
    {
        float2 acc[KK];
        float2 bias = *(const float2*)(bd2 + 2*dp);
        #pragma unroll
        for (int r = 0; r < KK; r++) acc[r] = bias;
        for (int j = 0; j < 128; j += 2){
            float2 w0 = *(float2*)(sW + (j+0)*128 + 2*dp);
            float2 w1 = *(float2*)(sW + (j+1)*128 + 2*dp);
            #pragma unroll
            for (int r = 0; r < KK; r++){
                float4 xv = *(float4*)(bufU + ((rg*KK+r)*128 + j)*2);
                acc[r] = ffma2(make_float2(xv.x,xv.y), w0, acc[r]);
                acc[r] = ffma2(make_float2(xv.z,xv.w), w1, acc[r]);
            }
        }
        #pragma unroll
        for (int r = 0; r < KK; r++)
            *(float2*)(g_pos + ((size_t)(p0+rg)*KK + r)*DM + 2*dp) = acc[r];
    }
}

// =================================================================
// Kernel 4: attention core. Persistent 148 blocks, 64-row tiles.
// t = q - fk[knn] + pos; h = relu(t@Wg1+bg1); a = h@Wg2+bg2;
// softmax over k (thread-local!); res = sum attn*(fv+pos).
// =================================================================
__global__ void __launch_bounds__(256, 1) attn_kernel(
    const float* __restrict__ Wg1, const float* __restrict__ bg1,
    const float* __restrict__ Wg2, const float* __restrict__ bg2)
{
    extern __shared__ float smD[];
    float* sW1  = smD;                // 16384
    float* sW2  = smD + 16384;        // 16384
    float* bufT = smD + 32768;        // 16384 (dup; t then h)
    float* spos = smD + 49152;        // 8192
    float* sq   = smD + 57344;        // 512
    int*   sidx = (int*)(smD + 57856);// 64

    int tid = threadIdx.x;
    for (int i = tid; i < 16384/4; i += 256){
        ((float4*)sW1)[i] = ((const float4*)Wg1)[i];
        ((float4*)sW2)[i] = ((const float4*)Wg2)[i];
    }
    int dp = tid & 63, rg = tid >> 6;
    float2 b1 = *(const float2*)(bg1 + 2*dp);
    float2 b2 = *(const float2*)(bg2 + 2*dp);
    const float invs = 0.08838834764831845f;   // 1/sqrt(128)

    for (int tile = blockIdx.x; tile < PTS/TILE_P; tile += gridDim.x){
        int p0 = tile * TILE_P;
        int base = p0 & ~(NN-1);
        __syncthreads();   // smem reuse guard (also covers first-iter weight load)
        if (tid < 64) sidx[tid] = g_knn[(size_t)p0*KK + tid];
        for (int i = tid; i < 256; i += 256)
            ((float2*)sq)[i] = ((const float2*)(g_q + (size_t)p0*DM))[i];
        for (int i = tid; i < 8192/4; i += 256)
            ((float4*)spos)[i] = ((const float4*)(g_pos + (size_t)p0*KK*DM))[i];
        __syncthreads();

        // t build (dup layout)
        float2 qv = *(float2*)(sq + rg*128 + 2*dp);
        #pragma unroll
        for (int r = 0; r < KK; r++){
            int nb = base + sidx[rg*KK + r];
            float2 kv = *(const float2*)(g_fk + (size_t)nb*DM + 2*dp);
            float2 pv = *(float2*)(spos + (rg*KK+r)*128 + 2*dp);
            float tx = qv.x - kv.x + pv.x;
            float ty = qv.y - kv.y + pv.y;
            *(float4*)(bufT + ((rg*KK+r)*128 + 2*dp)*2) = make_float4(tx, tx, ty, ty);
        }
        __syncthreads();

        // h = relu(t@Wg1 + bg1)
        float2 acc[KK];
        #pragma unroll
        for (int r = 0; r < KK; r++) acc[r] = b1;
        for (int j = 0; j < 128; j += 2){
            float2 w0 = *(float2*)(sW1 + (j+0)*128 + 2*dp);
            float2 w1 = *(float2*)(sW1 + (j+1)*128 + 2*dp);
            #pragma unroll
            for (int r = 0; r < KK; r++){
                float4 xv = *(float4*)(bufT + ((rg*KK+r)*128 + j)*2);
                acc[r] = ffma2(make_float2(xv.x,xv.y), w0, acc[r]);
                acc[r] = ffma2(make_float2(xv.z,xv.w), w1, acc[r]);
            }
        }
        __syncthreads();   // all t reads done
        #pragma unroll
        for (int r = 0; r < KK; r++){
            float hx = fmaxf(acc[r].x, 0.f), hy = fmaxf(acc[r].y, 0.f);
            *(float4*)(bufT + ((rg*KK+r)*128 + 2*dp)*2) = make_float4(hx, hx, hy, hy);
        }
        __syncthreads();

        // a = h@Wg2 + bg2 (registers only)
        #pragma unroll
        for (int r = 0; r < KK; r++) acc[r] = b2;
        for (int j = 0; j < 128; j += 2){
            float2 w0 = *(float2*)(sW2 + (j+0)*128 + 2*dp);
            float2 w1 = *(float2*)(sW2 + (j+1)*128 + 2*dp);
            #pragma unroll
            for (int r = 0; r < KK; r++){
                float4 xv = *(float4*)(bufT + ((rg*KK+r)*128 + j)*2);
                acc[r] = ffma2(make_float2(xv.x,xv.y), w0, acc[r]);
                acc[r] = ffma2(make_float2(xv.z,xv.w), w1, acc[r]);
            }
        }

        // softmax over k (thread-local) + weighted sum
        float mx = -3.4e38f, my = -3.4e38f;
        #pragma unroll
        for (int r = 0; r < KK; r++){ mx = fmaxf(mx, acc[r].x); my = fmaxf(my, acc[r].y); }
        float sx = 0.f, sy = 0.f;
        #pragma unroll
        for (int r = 0; r < KK; r++){
            acc[r].x = __expf((acc[r].x - mx)*invs); sx += acc[r].x;
            acc[r].y = __expf((acc[r].y - my)*invs); sy += acc[r].y;
        }
        float rsx = 1.f/sx, rsy = 1.f/sy;
        float resx = 0.f, resy = 0.f;
        #pragma unroll
        for (int r = 0; r < KK; r++){
            int nb = base + sidx[rg*KK + r];
            float2 fv = *(const float2*)(g_fv + (size_t)nb*DM + 2*dp);
            float2 pv = *(float2*)(spos + (rg*KK+r)*128 + 2*dp);
            resx += acc[r].x * (fv.x + pv.x);
            resy += acc[r].y * (fv.y + pv.y);
        }
        *(float2*)(g_res + (size_t)(p0+rg)*DM + 2*dp) = make_float2(resx*rsx, resy*rsy);
    }
}

// =================================================================
// Kernel 5: out = res@Wo + bo + shortcut. 128 rows/block, 128 blocks.
// =================================================================
__global__ void __launch_bounds__(256, 2) out_kernel(
    const float* __restrict__ features,
    const float* __restrict__ Wo, const float* __restrict__ bo,
    float* __restrict__ out)
{
    extern __shared__ float smE[];
    float* sWo = smE;          // 8192
    float* sr  = smE + 8192;   // 16384
    int tid = threadIdx.x;
    int row0 = blockIdx.x * 128;
    for (int i = tid; i < 8192/4;  i += 256) ((float4*)sWo)[i] = ((const float4*)Wo)[i];
    for (int i = tid; i < 16384/4; i += 256)
        ((float4*)sr)[i] = ((const float4*)(g_res + (size_t)row0*DM))[i];
    __syncthreads();

    int cp = tid & 31, rg = tid >> 5;   // 8 groups x 16 rows; 32 col-pairs
    float2 acc[16];
    float2 bias = *(const float2*)(bo + 2*cp);
    #pragma unroll
    for (int r = 0; r < 16; r++) acc[r] = bias;
    for (int j = 0; j < 128; j += 4){
        float2 w0 = *(float2*)(sWo + (j+0)*64 + 2*cp);
        float2 w1 = *(float2*)(sWo + (j+1)*64 + 2*cp);
        float2 w2 = *(float2*)(sWo + (j+2)*64 + 2*cp);
        float2 w3 = *(float2*)(sWo + (j+3)*64 + 2*cp);
        #pragma unroll
        for (int r = 0; r < 16; r++){
            float4 xv = *(float4*)(sr + (rg*16+r)*128 + j);
            acc[r] = ffma2(make_float2(xv.x,xv.x), w0, acc[r]);
            acc[r] = ffma2(make_float2(xv.y,xv.y), w1, acc[r]);
            acc[r] = ffma2(make_float2(xv.z,xv.z), w2, acc[r]);
            acc[r] = ffma2(make_float2(xv.w,xv.w), w3, acc[r]);
        }
    }
    #pragma unroll
    for (int r = 0; r < 16; r++){
        int p = row0 + rg*16 + r;
        float2 sc = *(const float2*)(features + (size_t)p*DP + 2*cp);
        *(float2*)(out + (size_t)p*DP + 2*cp) = make_float2(acc[r].x + sc.x, acc[r].y + sc.y);
    }
}

// =================================================================
extern "C" void kernel_launch(void* const* d_in, const int* in_sizes, int n_in,
                              void* d_out, int out_size)
{
    const float* xyz      = (const float*)d_in[0];
    const float* features = (const float*)d_in[1];
    const float* Wd1 = (const float*)d_in[2];  const float* bd1 = (const float*)d_in[3];
    const float* Wd2 = (const float*)d_in[4];  const float* bd2 = (const float*)d_in[5];
    const float* Wf1 = (const float*)d_in[6];  const float* bf1 = (const float*)d_in[7];
    const float* Wq  = (const float*)d_in[8];
    const float* Wk  = (const float*)d_in[9];
    const float* Wv  = (const float*)d_in[10];
    const float* Wg1 = (const float*)d_in[11]; const float* bg1 = (const float*)d_in[12];
    const float* Wg2 = (const float*)d_in[13]; const float* bg2 = (const float*)d_in[14];
    const float* Wo  = (const float*)d_in[15]; const float* bo  = (const float*)d_in[16];
    float* out = (float*)d_out;

    cudaFuncSetAttribute(knn_kernel,  cudaFuncAttributeMaxDynamicSharedMemorySize, 65536);
    cudaFuncSetAttribute(feat_kernel, cudaFuncAttributeMaxDynamicSharedMemorySize, 163840);
    cudaFuncSetAttribute(pos_kernel,  cudaFuncAttributeMaxDynamicSharedMemorySize, 131584);
    cudaFuncSetAttribute(attn_kernel, cudaFuncAttributeMaxDynamicSharedMemorySize, 231936);
    cudaFuncSetAttribute(out_kernel,  cudaFuncAttributeMaxDynamicSharedMemorySize, 98304);

    knn_kernel <<<dim3(64, 4), 256, 65536 >>>(xyz);
    feat_kernel<<<128, 256, 163840>>>(features, Wf1, bf1, Wq, Wk, Wv);
    pos_kernel <<<PTS/TILE_P, 256, 131584>>>(xyz, Wd1, bd1, Wd2, bd2);
    attn_kernel<<<148, 256, 231936>>>(Wg1, bg1, Wg2, bg2);
    out_kernel <<<PTS/128, 256, 98304>>>(features, Wo, bo, out);
}

// round 4
// speedup vs baseline: 1.6939x; 1.0471x over previous
#include <cuda_runtime.h>

#define BB 4
#define NN 4096
#define KK 16
#define DM 128
#define DP 64
#define PTS (BB*NN)      // 16384
#define NTILES (PTS/4)   // 4096 tiles of 64 rows

// ---------------- scratch (no allocations allowed) ----------------
__device__ int   g_knn[PTS*KK];            // 1 MB
__device__ float g_q  [PTS*DM];            // 8 MB
__device__ float g_fk [PTS*DM];            // 8 MB
__device__ float g_fv [PTS*DM];            // 8 MB
__device__ float g_pos[(size_t)PTS*KK*DM]; // 128 MB
__device__ float g_res[PTS*DM];            // 8 MB

// packed fp32x2 FMA (Blackwell): 2 fp32 FMAs per instruction
static __device__ __forceinline__ float2 ffma2(float2 a, float2 b, float2 c){
    float2 d;
    asm("fma.rn.f32x2 %0, %1, %2, %3;"
        : "=l"(reinterpret_cast<unsigned long long&>(d))
        : "l"(reinterpret_cast<unsigned long long&>(a)),
          "l"(reinterpret_cast<unsigned long long&>(b)),
          "l"(reinterpret_cast<unsigned long long&>(c)));
    return d;
}

// =================================================================
// Kernel 1: kNN. 8 queries/warp, 4 lanes/query, register-resident
// sorted top-16 per lane, quad shuffle merge. grid (64,4), 256 thr.
// =================================================================
__global__ void __launch_bounds__(256, 3) knn_kernel(const float* __restrict__ xyz)
{
    extern __shared__ float4 s4[];
    int b = blockIdx.y;
    const float* xb = xyz + (size_t)b*NN*3;
    for (int m = threadIdx.x; m < NN; m += blockDim.x){
        float x = xb[m*3+0], y = xb[m*3+1], z = xb[m*3+2];
        s4[m] = make_float4(x, y, z, x*x + y*y + z*z);
    }
    __syncthreads();

    int lane = threadIdx.x & 31;
    int warp = threadIdx.x >> 5;
    int quad = lane >> 2;
    int sl   = lane & 3;
    int q    = blockIdx.x*64 + warp*8 + quad;

    float4 qp = s4[q];
    float bd[KK]; int bi[KK];
    #pragma unroll
    for (int i = 0; i < KK; i++){ bd[i] = 3.4e38f; bi[i] = 0x7fffffff; }

    #pragma unroll 4
    for (int t = 0; t < NN/4; t++){
        int m = sl + 4*t;
        float4 c = s4[m];
        float d = qp.w + c.w;
        d = fmaf(-2.0f*c.x, qp.x, d);
        d = fmaf(-2.0f*c.y, qp.y, d);
        d = fmaf(-2.0f*c.z, qp.z, d);
        if (d < bd[KK-1]){
            float cd = d; int ci = m;
            #pragma unroll
            for (int i = 0; i < KK; i++){
                bool less = cd < bd[i];
                float nd = less ? cd : bd[i];
                int   ni = less ? ci : bi[i];
                float xd = less ? bd[i] : cd;
                int   xi = less ? bi[i] : ci;
                bd[i] = nd; bi[i] = ni; cd = xd; ci = xi;
            }
        }
    }

    int* outp = g_knn + ((size_t)b*NN + q)*KK;
    #pragma unroll 1
    for (int r = 0; r < KK; r++){
        float md = bd[0]; int mi = bi[0];
        float od; int oi;
        od = __shfl_xor_sync(0xffffffffu, md, 1); oi = __shfl_xor_sync(0xffffffffu, mi, 1);
        if (od < md || (od == md && oi < mi)){ md = od; mi = oi; }
        od = __shfl_xor_sync(0xffffffffu, md, 2); oi = __shfl_xor_sync(0xffffffffu, mi, 2);
        if (od < md || (od == md && oi < mi)){ md = od; mi = oi; }
        if (mi == bi[0] && md == bd[0]){
            #pragma unroll
            for (int i = 0; i < KK-1; i++){ bd[i] = bd[i+1]; bi[i] = bi[i+1]; }
            bd[KK-1] = 3.4e38f; bi[KK-1] = 0x7fffffff;
        }
        if (sl == 0) outp[r] = mi;
    }
}

// =================================================================
// Kernel 2: f=features@Wf1+bf1; q=f@Wq; fk=f@Wk; fv=f@Wv.
// 64-row tiles, warp-row/lane-channel GEMMs, broadcast-x.
// grid 256, 256 threads.
// =================================================================
__global__ void __launch_bounds__(256, 1) feat_kernel(
    const float* __restrict__ features,
    const float* __restrict__ Wf1, const float* __restrict__ bf1,
    const float* __restrict__ Wq,  const float* __restrict__ Wk,
    const float* __restrict__ Wv)
{
    extern __shared__ float sm2[];
    float2* sXd = (float2*)sm2;            // 64x64 dup  = 4096 f2 (8192 f)
    float2* sFd = (float2*)(sm2 + 8192);   // 64x128 dup = 8192 f2 (16384 f)
    float*  sW  = sm2 + 24576;             // 16384 f

    int tid  = threadIdx.x;
    int row0 = blockIdx.x * 64;
    int lane = tid & 31, warp = tid >> 5;
    int r0   = warp * 8;

    // features rows (dup) + Wf1
    for (int i = tid; i < 64*64/2; i += 256){
        float2 v = ((const float2*)(features + (size_t)row0*DP))[i];
        ((float4*)sXd)[i] = make_float4(v.x, v.x, v.y, v.y);
    }
    for (int i = tid; i < 64*128/4; i += 256)
        ((float4*)sW)[i] = ((const float4*)Wf1)[i];
    __syncthreads();

    // GEMM0: f = x@Wf1 + bf1  (K=64), f kept dup in sFd (own rows)
    {
        float4 bv = *(const float4*)(bf1 + 4*lane);
        float2 a0[8], a1[8];
        #pragma unroll
        for (int r = 0; r < 8; r++){ a0[r] = make_float2(bv.x, bv.y); a1[r] = make_float2(bv.z, bv.w); }
        for (int j = 0; j < 64; j++){
            float4 w = *(float4*)(sW + j*128 + 4*lane);
            float2 wa = make_float2(w.x, w.y), wb = make_float2(w.z, w.w);
            #pragma unroll
            for (int r = 0; r < 8; r++){
                float2 x = sXd[(r0+r)*64 + j];     // broadcast
                a0[r] = ffma2(x, wa, a0[r]);
                a1[r] = ffma2(x, wb, a1[r]);
            }
        }
        #pragma unroll
        for (int r = 0; r < 8; r++){
            *(float4*)(sFd + (r0+r)*128 + 4*lane + 0) = make_float4(a0[r].x, a0[r].x, a0[r].y, a0[r].y);
            *(float4*)(sFd + (r0+r)*128 + 4*lane + 2) = make_float4(a1[r].x, a1[r].x, a1[r].y, a1[r].y);
        }
        __syncwarp();
    }

    const float* Ws[3] = {Wq, Wk, Wv};
    float* Gs[3];
    Gs[0] = g_q; Gs[1] = g_fk; Gs[2] = g_fv;
    for (int wsel = 0; wsel < 3; wsel++){
        __syncthreads();                       // all warps done reading sW
        for (int i = tid; i < 128*128/4; i += 256)
            ((float4*)sW)[i] = ((const float4*)Ws[wsel])[i];
        __syncthreads();
        float2 a0[8], a1[8];
        #pragma unroll
        for (int r = 0; r < 8; r++){ a0[r] = make_float2(0.f,0.f); a1[r] = make_float2(0.f,0.f); }
        for (int j = 0; j < 128; j++){
            float4 w = *(float4*)(sW + j*128 + 4*lane);
            float2 wa = make_float2(w.x, w.y), wb = make_float2(w.z, w.w);
            #pragma unroll
            for (int r = 0; r < 8; r++){
                float2 x = sFd[(r0+r)*128 + j];    // broadcast
                a0[r] = ffma2(x, wa, a0[r]);
                a1[r] = ffma2(x, wb, a1[r]);
            }
        }
        float* gout = Gs[wsel];
        #pragma unroll
        for (int r = 0; r < 8; r++)
            *(float4*)(gout + (size_t)(row0 + r0 + r)*DM + 4*lane) =
                make_float4(a0[r].x, a0[r].y, a1[r].x, a1[r].y);
    }
}

// =================================================================
// Kernel 3: pos = relu(rel@Wd1+bd1)@Wd2+bd2. Persistent 148 blocks,
// Wd2 loaded once; 64-row tiles; broadcast-x GEMM.
// =================================================================
__global__ void __launch_bounds__(256, 1) pos_kernel(
    const float* __restrict__ xyz,
    const float* __restrict__ Wd1, const float* __restrict__ bd1,
    const float* __restrict__ Wd2, const float* __restrict__ bd2)
{
    extern __shared__ float smC[];
    float*  sW   = smC;                    // 16384
    float2* sU   = (float2*)(smC + 16384); // 8192 f2 (16384 f)
    int*    sidx = (int*)(smC + 32768);    // 64
    float*  sctr = smC + 32832;            // 16

    int tid = threadIdx.x;
    for (int i = tid; i < 16384/4; i += 256)
        ((float4*)sW)[i] = ((const float4*)Wd2)[i];

    int dp = tid & 63, rg = tid >> 6;
    int lane = tid & 31, warp = tid >> 5;
    int r0 = warp * 8;

    float2 bias1 = *(const float2*)(bd1 + 2*dp);
    float2 w0 = *(const float2*)(Wd1 +   0 + 2*dp);
    float2 w1 = *(const float2*)(Wd1 + 128 + 2*dp);
    float2 w2 = *(const float2*)(Wd1 + 256 + 2*dp);
    float4 bias2 = *(const float4*)(bd2 + 4*lane);

    for (int tile = blockIdx.x; tile < NTILES; tile += gridDim.x){
        int p0 = tile * 4;
        int base = p0 & ~(NN-1);
        __syncthreads();                     // sU/sidx reuse guard
        if (tid < 64) sidx[tid] = g_knn[(size_t)p0*KK + tid];
        if (tid < 12) sctr[tid] = xyz[(size_t)p0*3 + tid];
        __syncthreads();

        // stage 1: u = relu(rel@Wd1+bd1), dup, rows rg*16..rg*16+15
        float cx = sctr[rg*3+0], cy = sctr[rg*3+1], cz = sctr[rg*3+2];
        #pragma unroll
        for (int k = 0; k < KK; k++){
            int nb = base + sidx[rg*KK + k];
            float rx = cx - xyz[(size_t)nb*3+0];
            float ry = cy - xyz[(size_t)nb*3+1];
            float rz = cz - xyz[(size_t)nb*3+2];
            float2 acc = bias1;
            acc = ffma2(make_float2(rx,rx), w0, acc);
            acc = ffma2(make_float2(ry,ry), w1, acc);
            acc = ffma2(make_float2(rz,rz), w2, acc);
            float ax = fmaxf(acc.x, 0.f), ay = fmaxf(acc.y, 0.f);
            *(float4*)(sU + (rg*KK+k)*128 + 2*dp) = make_float4(ax, ax, ay, ay);
        }
        __syncthreads();

        // stage 2: pos = u@Wd2 + bd2 -> global (warp rows, lane channels)
        float2 a0[8], a1[8];
        #pragma unroll
        for (int r = 0; r < 8; r++){ a0[r] = make_float2(bias2.x, bias2.y); a1[r] = make_float2(bias2.z, bias2.w); }
        for (int j = 0; j < 128; j++){
            float4 w = *(float4*)(sW + j*128 + 4*lane);
            float2 wa = make_float2(w.x, w.y), wb = make_float2(w.z, w.w);
            #pragma unroll
            for (int r = 0; r < 8; r++){
                float2 x = sU[(r0+r)*128 + j];   // broadcast
                a0[r] = ffma2(x, wa, a0[r]);
                a1[r] = ffma2(x, wb, a1[r]);
            }
        }
        #pragma unroll
        for (int r = 0; r < 8; r++)
            *(float4*)(g_pos + ((size_t)tile*64 + r0 + r)*DM + 4*lane) =
                make_float4(a0[r].x, a0[r].y, a1[r].x, a1[r].y);
    }
}

// =================================================================
// Kernel 4: attention core. Persistent 148 blocks; Wg1/Wg2 loaded
// once; broadcast-x GEMMs; rows warp-private between GEMMs.
// =================================================================
__global__ void __launch_bounds__(256, 1) attn_kernel(
    const float* __restrict__ Wg1, const float* __restrict__ bg1,
    const float* __restrict__ Wg2, const float* __restrict__ bg2)
{
    extern __shared__ float smD[];
    float*  sW1  = smD;                     // 16384
    float*  sW2  = smD + 16384;             // 16384
    float2* sT   = (float2*)(smD + 32768);  // 8192 f2 (16384 f)
    float*  sPos = smD + 49152;             // 8192
    int*    sidx = (int*)(smD + 57344);     // 64

    int tid = threadIdx.x;
    for (int i = tid; i < 16384/4; i += 256){
        ((float4*)sW1)[i] = ((const float4*)Wg1)[i];
        ((float4*)sW2)[i] = ((const float4*)Wg2)[i];
    }
    int dp = tid & 63, rg = tid >> 6;
    int lane = tid & 31, warp = tid >> 5;
    int r0 = warp * 8;
    const float invs = 0.08838834764831845f;   // 1/sqrt(128)
    float4 bv1 = *(const float4*)(bg1 + 4*lane);
    float4 bv2 = *(const float4*)(bg2 + 4*lane);

    for (int tile = blockIdx.x; tile < NTILES; tile += gridDim.x){
        int p0 = tile * 4;
        int base = p0 & ~(NN-1);
        __syncthreads();                       // smem reuse guard
        if (tid < 64) sidx[tid] = g_knn[(size_t)p0*KK + tid];
        for (int i = tid; i < 8192/4; i += 256)
            ((float4*)sPos)[i] = ((const float4*)(g_pos + (size_t)tile*64*DM))[i];
        __syncthreads();

        // ---- t = q - fk[knn] + pos  (dup into sT) ----
        {
            float2 qv = *(const float2*)(g_q + (size_t)(p0+rg)*DM + 2*dp);
            #pragma unroll
            for (int k = 0; k < KK; k++){
                int nb = base + sidx[rg*KK + k];
                float2 kv = *(const float2*)(g_fk + (size_t)nb*DM + 2*dp);
                int row = rg*KK + k;
                float px = sPos[row*128 + 2*dp], py = sPos[row*128 + 2*dp + 1];
                float tx = qv.x - kv.x + px;
                float ty = qv.y - kv.y + py;
                *(float4*)(sT + row*128 + 2*dp) = make_float4(tx, tx, ty, ty);
            }
        }
        __syncthreads();

        // ---- GEMM1: h = relu(t@Wg1+bg1), rows warp-private ----
        float2 a0[8], a1[8];
        #pragma unroll
        for (int r = 0; r < 8; r++){ a0[r] = make_float2(bv1.x, bv1.y); a1[r] = make_float2(bv1.z, bv1.w); }
        for (int j = 0; j < 128; j++){
            float4 w = *(float4*)(sW1 + j*128 + 4*lane);
            float2 wa = make_float2(w.x, w.y), wb = make_float2(w.z, w.w);
            #pragma unroll
            for (int r = 0; r < 8; r++){
                float2 x = sT[(r0+r)*128 + j];   // broadcast
                a0[r] = ffma2(x, wa, a0[r]);
                a1[r] = ffma2(x, wb, a1[r]);
            }
        }
        #pragma unroll
        for (int r = 0; r < 8; r++){
            float h0 = fmaxf(a0[r].x, 0.f), h1 = fmaxf(a0[r].y, 0.f);
            float h2 = fmaxf(a1[r].x, 0.f), h3 = fmaxf(a1[r].y, 0.f);
            *(float4*)(sT + (r0+r)*128 + 4*lane + 0) = make_float4(h0, h0, h1, h1);
            *(float4*)(sT + (r0+r)*128 + 4*lane + 2) = make_float4(h2, h2, h3, h3);
        }
        __syncwarp();

        // ---- GEMM2: a = h@Wg2+bg2 ----
        #pragma unroll
        for (int r = 0; r < 8; r++){ a0[r] = make_float2(bv2.x, bv2.y); a1[r] = make_float2(bv2.z, bv2.w); }
        for (int j = 0; j < 128; j++){
            float4 w = *(float4*)(sW2 + j*128 + 4*lane);
            float2 wa = make_float2(w.x, w.y), wb = make_float2(w.z, w.w);
            #pragma unroll
            for (int r = 0; r < 8; r++){
                float2 x = sT[(r0+r)*128 + j];   // broadcast
                a0[r] = ffma2(x, wa, a0[r]);
                a1[r] = ffma2(x, wb, a1[r]);
            }
        }
        #pragma unroll
        for (int r = 0; r < 8; r++){             // own rows: no pre-sync needed
            *(float4*)(sT + (r0+r)*128 + 4*lane + 0) = make_float4(a0[r].x, a0[r].x, a0[r].y, a0[r].y);
            *(float4*)(sT + (r0+r)*128 + 4*lane + 2) = make_float4(a1[r].x, a1[r].x, a1[r].y, a1[r].y);
        }
        __syncthreads();

        // ---- softmax over k (thread-local) + weighted sum ----
        {
            float y0[KK], y1[KK];
            float mx = -3.4e38f, my = -3.4e38f;
            #pragma unroll
            for (int k = 0; k < KK; k++){
                int row = rg*KK + k;
                y0[k] = sT[row*128 + 2*dp    ].x;
                y1[k] = sT[row*128 + 2*dp + 1].x;
                mx = fmaxf(mx, y0[k]); my = fmaxf(my, y1[k]);
            }
            float sx = 0.f, sy = 0.f;
            #pragma unroll
            for (int k = 0; k < KK; k++){
                y0[k] = __expf((y0[k] - mx)*invs); sx += y0[k];
                y1[k] = __expf((y1[k] - my)*invs); sy += y1[k];
            }
            float rsx = 1.f/sx, rsy = 1.f/sy;
            float resx = 0.f, resy = 0.f;
            #pragma unroll
            for (int k = 0; k < KK; k++){
                int nb = base + sidx[rg*KK + k];
                float2 fv = *(const float2*)(g_fv + (size_t)nb*DM + 2*dp);
                int row = rg*KK + k;
                resx += y0[k] * (fv.x + sPos[row*128 + 2*dp]);
                resy += y1[k] * (fv.y + sPos[row*128 + 2*dp + 1]);
            }
            *(float2*)(g_res + (size_t)(p0+rg)*DM + 2*dp) = make_float2(resx*rsx, resy*rsy);
        }
    }
}

// =================================================================
// Kernel 5: out = res@Wo + bo + shortcut. 64-row tiles, grid 256.
// =================================================================
__global__ void __launch_bounds__(256, 2) out_kernel(
    const float* __restrict__ features,
    const float* __restrict__ Wo, const float* __restrict__ bo,
    float* __restrict__ out)
{
    extern __shared__ float smE[];
    float2* sRd = (float2*)smE;        // 64x128 dup = 8192 f2 (16384 f)
    float*  sWo = smE + 16384;         // 8192
    int tid = threadIdx.x;
    int row0 = blockIdx.x * 64;
    int lane = tid & 31, warp = tid >> 5;
    int r0 = warp * 8;

    for (int i = tid; i < 64*128/2; i += 256){
        float2 v = ((const float2*)(g_res + (size_t)row0*DM))[i];
        ((float4*)sRd)[i] = make_float4(v.x, v.x, v.y, v.y);
    }
    for (int i = tid; i < 8192/4; i += 256)
        ((float4*)sWo)[i] = ((const float4*)Wo)[i];
    __syncthreads();

    float2 acc[8];
    float2 bias = *(const float2*)(bo + 2*lane);
    #pragma unroll
    for (int r = 0; r < 8; r++) acc[r] = bias;
    for (int j = 0; j < 128; j++){
        float2 w = *(float2*)(sWo + j*64 + 2*lane);
        #pragma unroll
        for (int r = 0; r < 8; r++){
            float2 x = sRd[(r0+r)*128 + j];   // broadcast
            acc[r] = ffma2(x, w, acc[r]);
        }
    }
    #pragma unroll
    for (int r = 0; r < 8; r++){
        int p = row0 + r0 + r;
        float2 sc = *(const float2*)(features + (size_t)p*DP + 2*lane);
        *(float2*)(out + (size_t)p*DP + 2*lane) = make_float2(acc[r].x + sc.x, acc[r].y + sc.y);
    }
}

// =================================================================
extern "C" void kernel_launch(void* const* d_in, const int* in_sizes, int n_in,
                              void* d_out, int out_size)
{
    const float* xyz      = (const float*)d_in[0];
    const float* features = (const float*)d_in[1];
    const float* Wd1 = (const float*)d_in[2];  const float* bd1 = (const float*)d_in[3];
    const float* Wd2 = (const float*)d_in[4];  const float* bd2 = (const float*)d_in[5];
    const float* Wf1 = (const float*)d_in[6];  const float* bf1 = (const float*)d_in[7];
    const float* Wq  = (const float*)d_in[8];
    const float* Wk  = (const float*)d_in[9];
    const float* Wv  = (const float*)d_in[10];
    const float* Wg1 = (const float*)d_in[11]; const float* bg1 = (const float*)d_in[12];
    const float* Wg2 = (const float*)d_in[13]; const float* bg2 = (const float*)d_in[14];
    const float* Wo  = (const float*)d_in[15]; const float* bo  = (const float*)d_in[16];
    float* out = (float*)d_out;

    cudaFuncSetAttribute(knn_kernel,  cudaFuncAttributeMaxDynamicSharedMemorySize, 65536);
    cudaFuncSetAttribute(feat_kernel, cudaFuncAttributeMaxDynamicSharedMemorySize, 163840);
    cudaFuncSetAttribute(pos_kernel,  cudaFuncAttributeMaxDynamicSharedMemorySize, 131392);
    cudaFuncSetAttribute(attn_kernel, cudaFuncAttributeMaxDynamicSharedMemorySize, 229632);
    cudaFuncSetAttribute(out_kernel,  cudaFuncAttributeMaxDynamicSharedMemorySize, 98304);

    knn_kernel <<<dim3(64, 4), 256, 65536 >>>(xyz);
    feat_kernel<<<PTS/64, 256, 163840>>>(features, Wf1, bf1, Wq, Wk, Wv);
    pos_kernel <<<148, 256, 131392>>>(xyz, Wd1, bd1, Wd2, bd2);
    attn_kernel<<<148, 256, 229632>>>(Wg1, bg1, Wg2, bg2);
    out_kernel <<<PTS/64, 256, 98304>>>(features, Wo, bo, out);
}

// round 6
// speedup vs baseline: 1.7547x; 1.0359x over previous
#include <cuda_runtime.h>

#define BB 4
#define NN 4096
#define KK 16
#define DM 128
#define DP 64
#define PTS (BB*NN)      // 16384
#define NTILES (PTS/4)   // 4096 tiles of 64 rows

// ---------------- scratch (no allocations allowed) ----------------
__device__ int   g_knn[PTS*KK];            // 1 MB
__device__ float g_q  [PTS*DM];            // 8 MB
__device__ float g_fk [PTS*DM];            // 8 MB
__device__ float g_fv [PTS*DM];            // 8 MB
__device__ float g_pos[(size_t)PTS*KK*DM]; // 128 MB
__device__ float g_res[PTS*DM];            // 8 MB

// packed fp32x2 FMA (Blackwell): 2 fp32 FMAs per instruction
static __device__ __forceinline__ float2 ffma2(float2 a, float2 b, float2 c){
    float2 d;
    asm("fma.rn.f32x2 %0, %1, %2, %3;"
        : "=l"(reinterpret_cast<unsigned long long&>(d))
        : "l"(reinterpret_cast<unsigned long long&>(a)),
          "l"(reinterpret_cast<unsigned long long&>(b)),
          "l"(reinterpret_cast<unsigned long long&>(c)));
    return d;
}

// =================================================================
// Kernel 1: kNN. grid (64,4), 256 threads.
// =================================================================
__global__ void __launch_bounds__(256, 3) knn_kernel(const float* __restrict__ xyz)
{
    extern __shared__ float4 s4[];
    int b = blockIdx.y;
    const float* xb = xyz + (size_t)b*NN*3;
    for (int m = threadIdx.x; m < NN; m += blockDim.x){
        float x = xb[m*3+0], y = xb[m*3+1], z = xb[m*3+2];
        s4[m] = make_float4(x, y, z, x*x + y*y + z*z);
    }
    __syncthreads();

    int lane = threadIdx.x & 31;
    int warp = threadIdx.x >> 5;
    int quad = lane >> 2;
    int sl   = lane & 3;
    int q    = blockIdx.x*64 + warp*8 + quad;

    float4 qp = s4[q];
    float bd[KK]; int bi[KK];
    #pragma unroll
    for (int i = 0; i < KK; i++){ bd[i] = 3.4e38f; bi[i] = 0x7fffffff; }

    #pragma unroll 4
    for (int t = 0; t < NN/4; t++){
        int m = sl + 4*t;
        float4 c = s4[m];
        float d = qp.w + c.w;
        d = fmaf(-2.0f*c.x, qp.x, d);
        d = fmaf(-2.0f*c.y, qp.y, d);
        d = fmaf(-2.0f*c.z, qp.z, d);
        if (d < bd[KK-1]){
            float cd = d; int ci = m;
            #pragma unroll
            for (int i = 0; i < KK; i++){
                bool less = cd < bd[i];
                float nd = less ? cd : bd[i];
                int   ni = less ? ci : bi[i];
                float xd = less ? bd[i] : cd;
                int   xi = less ? bi[i] : ci;
                bd[i] = nd; bi[i] = ni; cd = xd; ci = xi;
            }
        }
    }

    int* outp = g_knn + ((size_t)b*NN + q)*KK;
    #pragma unroll 1
    for (int r = 0; r < KK; r++){
        float md = bd[0]; int mi = bi[0];
        float od; int oi;
        od = __shfl_xor_sync(0xffffffffu, md, 1); oi = __shfl_xor_sync(0xffffffffu, mi, 1);
        if (od < md || (od == md && oi < mi)){ md = od; mi = oi; }
        od = __shfl_xor_sync(0xffffffffu, md, 2); oi = __shfl_xor_sync(0xffffffffu, mi, 2);
        if (od < md || (od == md && oi < mi)){ md = od; mi = oi; }
        if (mi == bi[0] && md == bd[0]){
            #pragma unroll
            for (int i = 0; i < KK-1; i++){ bd[i] = bd[i+1]; bi[i] = bi[i+1]; }
            bd[KK-1] = 3.4e38f; bi[KK-1] = 0x7fffffff;
        }
        if (sl == 0) outp[r] = mi;
    }
}

// =================================================================
// Kernel 2: f=features@Wf1+bf1; q=f@Wq; fk=f@Wk; fv=f@Wv.
// 512 threads, 16 warps x 4 rows, 4 ch/lane, 2j per iter.
// =================================================================
__global__ void __launch_bounds__(512, 1) feat_kernel(
    const float* __restrict__ features,
    const float* __restrict__ Wf1, const float* __restrict__ bf1,
    const float* __restrict__ Wq,  const float* __restrict__ Wk,
    const float* __restrict__ Wv)
{
    extern __shared__ float sm2[];
    float2* sXd = (float2*)sm2;            // 64x64 dup  = 4096 f2
    float2* sFd = (float2*)(sm2 + 8192);   // 64x128 dup = 8192 f2
    float*  sW  = sm2 + 24576;             // 16384 f

    int tid  = threadIdx.x;
    int row0 = blockIdx.x * 64;
    int lane = tid & 31, warp = tid >> 5;
    int r0   = warp * 4;

    for (int i = tid; i < 64*64/2; i += 512){
        float2 v = ((const float2*)(features + (size_t)row0*DP))[i];
        ((float4*)sXd)[i] = make_float4(v.x, v.x, v.y, v.y);
    }
    for (int i = tid; i < 64*128/4; i += 512)
        ((float4*)sW)[i] = ((const float4*)Wf1)[i];
    __syncthreads();

    // GEMM0: f = x@Wf1 + bf1 (K=64) -> sFd dup (own rows)
    {
        float4 bv = *(const float4*)(bf1 + 4*lane);
        float2 a0[4], a1[4];
        #pragma unroll
        for (int r = 0; r < 4; r++){ a0[r] = make_float2(bv.x, bv.y); a1[r] = make_float2(bv.z, bv.w); }
        #pragma unroll 4
        for (int j = 0; j < 64; j += 2){
            float4 w0 = *(float4*)(sW + (j+0)*128 + 4*lane);
            float4 w1 = *(float4*)(sW + (j+1)*128 + 4*lane);
            #pragma unroll
            for (int r = 0; r < 4; r++){
                float4 xv = *(float4*)(sXd + (r0+r)*64 + j);   // (xj,xj,xj1,xj1) broadcast
                a0[r] = ffma2(make_float2(xv.x,xv.y), make_float2(w0.x,w0.y), a0[r]);
                a1[r] = ffma2(make_float2(xv.x,xv.y), make_float2(w0.z,w0.w), a1[r]);
                a0[r] = ffma2(make_float2(xv.z,xv.w), make_float2(w1.x,w1.y), a0[r]);
                a1[r] = ffma2(make_float2(xv.z,xv.w), make_float2(w1.z,w1.w), a1[r]);
            }
        }
        #pragma unroll
        for (int r = 0; r < 4; r++){
            *(float4*)(sFd + (r0+r)*128 + 4*lane + 0) = make_float4(a0[r].x, a0[r].x, a0[r].y, a0[r].y);
            *(float4*)(sFd + (r0+r)*128 + 4*lane + 2) = make_float4(a1[r].x, a1[r].x, a1[r].y, a1[r].y);
        }
        __syncwarp();
    }

    const float* Ws[3] = {Wq, Wk, Wv};
    float* Gs[3];
    Gs[0] = g_q; Gs[1] = g_fk; Gs[2] = g_fv;
    for (int wsel = 0; wsel < 3; wsel++){
        __syncthreads();
        for (int i = tid; i < 128*128/4; i += 512)
            ((float4*)sW)[i] = ((const float4*)Ws[wsel])[i];
        __syncthreads();
        float2 a0[4], a1[4];
        #pragma unroll
        for (int r = 0; r < 4; r++){ a0[r] = make_float2(0.f,0.f); a1[r] = make_float2(0.f,0.f); }
        #pragma unroll 4
        for (int j = 0; j < 128; j += 2){
            float4 w0 = *(float4*)(sW + (j+0)*128 + 4*lane);
            float4 w1 = *(float4*)(sW + (j+1)*128 + 4*lane);
            #pragma unroll
            for (int r = 0; r < 4; r++){
                float4 xv = *(float4*)(sFd + (r0+r)*128 + j);
                a0[r] = ffma2(make_float2(xv.x,xv.y), make_float2(w0.x,w0.y), a0[r]);
                a1[r] = ffma2(make_float2(xv.x,xv.y), make_float2(w0.z,w0.w), a1[r]);
                a0[r] = ffma2(make_float2(xv.z,xv.w), make_float2(w1.x,w1.y), a0[r]);
                a1[r] = ffma2(make_float2(xv.z,xv.w), make_float2(w1.z,w1.w), a1[r]);
            }
        }
        float* gout = Gs[wsel];
        #pragma unroll
        for (int r = 0; r < 4; r++)
            *(float4*)(gout + (size_t)(row0 + r0 + r)*DM + 4*lane) =
                make_float4(a0[r].x, a0[r].y, a1[r].x, a1[r].y);
    }
}

// =================================================================
// Kernel 3: pos = relu(rel@Wd1+bd1)@Wd2+bd2. Persistent 148 blocks,
// 512 threads; Wd2 loaded once; 2j-float4 GEMM.
// =================================================================
__global__ void __launch_bounds__(512, 1) pos_kernel(
    const float* __restrict__ xyz,
    const float* __restrict__ Wd1, const float* __restrict__ bd1,
    const float* __restrict__ Wd2, const float* __restrict__ bd2)
{
    extern __shared__ float smC[];
    float*  sW   = smC;                    // 16384 f
    float2* sU   = (float2*)(smC + 16384); // 8192 f2
    int*    sidx = (int*)(smC + 32768);    // 64
    float*  sctr = smC + 32832;            // 16

    int tid = threadIdx.x;
    for (int i = tid; i < 16384/4; i += 512)
        ((float4*)sW)[i] = ((const float4*)Wd2)[i];

    int lane = tid & 31, warp = tid >> 5;
    int r0 = warp * 4;
    int c = tid & 127, rg = tid >> 7;

    float w0c = Wd1[      c], w1c = Wd1[128 + c], w2c = Wd1[256 + c];
    float b1c = bd1[c];
    float4 bias2 = *(const float4*)(bd2 + 4*lane);

    for (int tile = blockIdx.x; tile < NTILES; tile += gridDim.x){
        int p0 = tile * 4;
        int base = p0 & ~(NN-1);
        __syncthreads();
        if (tid < 64) sidx[tid] = g_knn[(size_t)p0*KK + tid];
        if (tid < 12) sctr[tid] = xyz[(size_t)p0*3 + tid];
        __syncthreads();

        // stage 1: u = relu(rel@Wd1+bd1) dup; thread (rg, c)
        {
            float cx = sctr[rg*3+0], cy = sctr[rg*3+1], cz = sctr[rg*3+2];
            #pragma unroll
            for (int k = 0; k < KK; k++){
                int nb = base + sidx[rg*KK + k];
                float rx = cx - xyz[(size_t)nb*3+0];
                float ry = cy - xyz[(size_t)nb*3+1];
                float rz = cz - xyz[(size_t)nb*3+2];
                float u = b1c;
                u = fmaf(rx, w0c, u);
                u = fmaf(ry, w1c, u);
                u = fmaf(rz, w2c, u);
                u = fmaxf(u, 0.f);
                sU[(rg*KK+k)*128 + c] = make_float2(u, u);
            }
        }
        __syncthreads();

        // stage 2: pos = u@Wd2 + bd2 -> global
        float2 a0[4], a1[4];
        #pragma unroll
        for (int r = 0; r < 4; r++){ a0[r] = make_float2(bias2.x, bias2.y); a1[r] = make_float2(bias2.z, bias2.w); }
        #pragma unroll 4
        for (int j = 0; j < 128; j += 2){
            float4 w0 = *(float4*)(sW + (j+0)*128 + 4*lane);
            float4 w1 = *(float4*)(sW + (j+1)*128 + 4*lane);
            #pragma unroll
            for (int r = 0; r < 4; r++){
                float4 xv = *(float4*)(sU + (r0+r)*128 + j);
                a0[r] = ffma2(make_float2(xv.x,xv.y), make_float2(w0.x,w0.y), a0[r]);
                a1[r] = ffma2(make_float2(xv.x,xv.y), make_float2(w0.z,w0.w), a1[r]);
                a0[r] = ffma2(make_float2(xv.z,xv.w), make_float2(w1.x,w1.y), a0[r]);
                a1[r] = ffma2(make_float2(xv.z,xv.w), make_float2(w1.z,w1.w), a1[r]);
            }
        }
        #pragma unroll
        for (int r = 0; r < 4; r++)
            *(float4*)(g_pos + ((size_t)tile*64 + r0 + r)*DM + 4*lane) =
                make_float4(a0[r].x, a0[r].y, a1[r].x, a1[r].y);
    }
}

// =================================================================
// Kernel 4: attention core. Persistent 148 blocks, 512 threads;
// Wg1/Wg2 loaded once; 2j-float4 GEMMs; rows warp-private.
// =================================================================
__global__ void __launch_bounds__(512, 1) attn_kernel(
    const float* __restrict__ Wg1, const float* __restrict__ bg1,
    const float* __restrict__ Wg2, const float* __restrict__ bg2)
{
    extern __shared__ float smD[];
    float*  sW1  = smD;                     // 16384 f
    float*  sW2  = smD + 16384;             // 16384 f
    float2* sT   = (float2*)(smD + 32768);  // 8192 f2 (dup t/h)
    float*  sTf  = smD + 32768;             // plain alias (a, 64x128 f)
    float*  sPos = smD + 49152;             // 8192 f
    int*    sidx = (int*)(smD + 57344);     // 64

    int tid = threadIdx.x;
    for (int i = tid; i < 16384/4; i += 512){
        ((float4*)sW1)[i] = ((const float4*)Wg1)[i];
        ((float4*)sW2)[i] = ((const float4*)Wg2)[i];
    }
    int lane = tid & 31, warp = tid >> 5;
    int r0 = warp * 4;
    int c = tid & 127, rg = tid >> 7;
    const float invs = 0.08838834764831845f;   // 1/sqrt(128)
    float4 bv1 = *(const float4*)(bg1 + 4*lane);
    float4 bv2 = *(const float4*)(bg2 + 4*lane);

    for (int tile = blockIdx.x; tile < NTILES; tile += gridDim.x){
        int p0 = tile * 4;
        int base = p0 & ~(NN-1);
        __syncthreads();                       // smem reuse guard
        if (tid < 64) sidx[tid] = g_knn[(size_t)p0*KK + tid];
        for (int i = tid; i < 8192/4; i += 512)
            ((float4*)sPos)[i] = ((const float4*)(g_pos + (size_t)tile*64*DM))[i];
        __syncthreads();

        // ---- t = q - fk[knn] + pos  (dup); thread (rg, c) ----
        {
            float qv = g_q[(size_t)(p0+rg)*DM + c];
            #pragma unroll
            for (int k = 0; k < KK; k++){
                int nb = base + sidx[rg*KK + k];
                float kv = g_fk[(size_t)nb*DM + c];
                int row = rg*KK + k;
                float t = qv - kv + sPos[row*128 + c];
                sT[row*128 + c] = make_float2(t, t);
            }
        }
        __syncthreads();

        // ---- GEMM1: h = relu(t@Wg1+bg1) ----
        float2 a0[4], a1[4];
        #pragma unroll
        for (int r = 0; r < 4; r++){ a0[r] = make_float2(bv1.x, bv1.y); a1[r] = make_float2(bv1.z, bv1.w); }
        #pragma unroll 4
        for (int j = 0; j < 128; j += 2){
            float4 w0 = *(float4*)(sW1 + (j+0)*128 + 4*lane);
            float4 w1 = *(float4*)(sW1 + (j+1)*128 + 4*lane);
            #pragma unroll
            for (int r = 0; r < 4; r++){
                float4 xv = *(float4*)(sT + (r0+r)*128 + j);
                a0[r] = ffma2(make_float2(xv.x,xv.y), make_float2(w0.x,w0.y), a0[r]);
                a1[r] = ffma2(make_float2(xv.x,xv.y), make_float2(w0.z,w0.w), a1[r]);
                a0[r] = ffma2(make_float2(xv.z,xv.w), make_float2(w1.x,w1.y), a0[r]);
                a1[r] = ffma2(make_float2(xv.z,xv.w), make_float2(w1.z,w1.w), a1[r]);
            }
        }
        #pragma unroll
        for (int r = 0; r < 4; r++){
            float h0 = fmaxf(a0[r].x, 0.f), h1 = fmaxf(a0[r].y, 0.f);
            float h2 = fmaxf(a1[r].x, 0.f), h3 = fmaxf(a1[r].y, 0.f);
            *(float4*)(sT + (r0+r)*128 + 4*lane + 0) = make_float4(h0, h0, h1, h1);
            *(float4*)(sT + (r0+r)*128 + 4*lane + 2) = make_float4(h2, h2, h3, h3);
        }
        __syncwarp();

        // ---- GEMM2: a = h@Wg2+bg2 ----
        #pragma unroll
        for (int r = 0; r < 4; r++){ a0[r] = make_float2(bv2.x, bv2.y); a1[r] = make_float2(bv2.z, bv2.w); }
        #pragma unroll 4
        for (int j = 0; j < 128; j += 2){
            float4 w0 = *(float4*)(sW2 + (j+0)*128 + 4*lane);
            float4 w1 = *(float4*)(sW2 + (j+1)*128 + 4*lane);
            #pragma unroll
            for (int r = 0; r < 4; r++){
                float4 xv = *(float4*)(sT + (r0+r)*128 + j);
                a0[r] = ffma2(make_float2(xv.x,xv.y), make_float2(w0.x,w0.y), a0[r]);
                a1[r] = ffma2(make_float2(xv.x,xv.y), make_float2(w0.z,w0.w), a1[r]);
                a0[r] = ffma2(make_float2(xv.z,xv.w), make_float2(w1.x,w1.y), a0[r]);
                a1[r] = ffma2(make_float2(xv.z,xv.w), make_float2(w1.z,w1.w), a1[r]);
            }
        }
        __syncthreads();           // all dup reads done before plain overwrite
        #pragma unroll
        for (int r = 0; r < 4; r++)
            *(float4*)(sTf + (r0+r)*128 + 4*lane) =
                make_float4(a0[r].x, a0[r].y, a1[r].x, a1[r].y);
        __syncthreads();

        // ---- softmax over k + weighted sum; thread (rg, c) ----
        {
            float y[KK];
            float mx = -3.4e38f;
            #pragma unroll
            for (int k = 0; k < KK; k++){
                y[k] = sTf[(rg*KK+k)*128 + c];
                mx = fmaxf(mx, y[k]);
            }
            float s = 0.f;
            #pragma unroll
            for (int k = 0; k < KK; k++){
                y[k] = __expf((y[k] - mx)*invs); s += y[k];
            }
            float inv_s = 1.f / s;
            float res = 0.f;
            #pragma unroll
            for (int k = 0; k < KK; k++){
                int nb = base + sidx[rg*KK + k];
                float fv = g_fv[(size_t)nb*DM + c];
                res += y[k] * (fv + sPos[(rg*KK+k)*128 + c]);
            }
            g_res[(size_t)(p0+rg)*DM + c] = res * inv_s;
        }
    }
}

// =================================================================
// Kernel 5: out = res@Wo + bo + shortcut. 64-row tiles, grid 256.
// =================================================================
__global__ void __launch_bounds__(256, 2) out_kernel(
    const float* __restrict__ features,
    const float* __restrict__ Wo, const float* __restrict__ bo,
    float* __restrict__ out)
{
    extern __shared__ float smE[];
    float2* sRd = (float2*)smE;        // 64x128 dup = 8192 f2
    float*  sWo = smE + 16384;         // 8192
    int tid = threadIdx.x;
    int row0 = blockIdx.x * 64;
    int lane = tid & 31, warp = tid >> 5;
    int r0 = warp * 8;

    for (int i = tid; i < 64*128/2; i += 256){
        float2 v = ((const float2*)(g_res + (size_t)row0*DM))[i];
        ((float4*)sRd)[i] = make_float4(v.x, v.x, v.y, v.y);
    }
    for (int i = tid; i < 8192/4; i += 256)
        ((float4*)sWo)[i] = ((const float4*)Wo)[i];
    __syncthreads();

    float2 acc[8];
    float2 bias = *(const float2*)(bo + 2*lane);
    #pragma unroll
    for (int r = 0; r < 8; r++) acc[r] = bias;
    #pragma unroll 4
    for (int j = 0; j < 128; j += 2){
        float2 w0 = *(float2*)(sWo + (j+0)*64 + 2*lane);
        float2 w1 = *(float2*)(sWo + (j+1)*64 + 2*lane);
        #pragma unroll
        for (int r = 0; r < 8; r++){
            float4 xv = *(float4*)(sRd + (r0+r)*128 + j);
            acc[r] = ffma2(make_float2(xv.x,xv.y), w0, acc[r]);
            acc[r] = ffma2(make_float2(xv.z,xv.w), w1, acc[r]);
        }
    }
    #pragma unroll
    for (int r = 0; r < 8; r++){
        int p = row0 + r0 + r;
        float2 sc = *(const float2*)(features + (size_t)p*DP + 2*lane);
        *(float2*)(out + (size_t)p*DP + 2*lane) = make_float2(acc[r].x + sc.x, acc[r].y + sc.y);
    }
}

// =================================================================
extern "C" void kernel_launch(void* const* d_in, const int* in_sizes, int n_in,
                              void* d_out, int out_size)
{
    const float* xyz      = (const float*)d_in[0];
    const float* features = (const float*)d_in[1];
    const float* Wd1 = (const float*)d_in[2];  const float* bd1 = (const float*)d_in[3];
    const float* Wd2 = (const float*)d_in[4];  const float* bd2 = (const float*)d_in[5];
    const float* Wf1 = (const float*)d_in[6];  const float* bf1 = (const float*)d_in[7];
    const float* Wq  = (const float*)d_in[8];
    const float* Wk  = (const float*)d_in[9];
    const float* Wv  = (const float*)d_in[10];
    const float* Wg1 = (const float*)d_in[11]; const float* bg1 = (const float*)d_in[12];
    const float* Wg2 = (const float*)d_in[13]; const float* bg2 = (const float*)d_in[14];
    const float* Wo  = (const float*)d_in[15]; const float* bo  = (const float*)d_in[16];
    float* out = (float*)d_out;

    cudaFuncSetAttribute(knn_kernel,  cudaFuncAttributeMaxDynamicSharedMemorySize, 65536);
    cudaFuncSetAttribute(feat_kernel, cudaFuncAttributeMaxDynamicSharedMemorySize, 163840);
    cudaFuncSetAttribute(pos_kernel,  cudaFuncAttributeMaxDynamicSharedMemorySize, 131392);
    cudaFuncSetAttribute(attn_kernel, cudaFuncAttributeMaxDynamicSharedMemorySize, 229632);
    cudaFuncSetAttribute(out_kernel,  cudaFuncAttributeMaxDynamicSharedMemorySize, 98304);

    knn_kernel <<<dim3(64, 4), 256, 65536 >>>(xyz);
    feat_kernel<<<PTS/64, 512, 163840>>>(features, Wf1, bf1, Wq, Wk, Wv);
    pos_kernel <<<148, 512, 131392>>>(xyz, Wd1, bd1, Wd2, bd2);
    attn_kernel<<<148, 512, 229632>>>(Wg1, bg1, Wg2, bg2);
    out_kernel <<<PTS/64, 256, 98304>>>(features, Wo, bo, out);
}

// round 17
// speedup vs baseline: 2.2715x; 1.2945x over previous
#include <cuda_runtime.h>
#include <cuda_bf16.h>
#include <cstdint>

#define BB 4
#define NN 4096
#define KK 16
#define DM 128
#define DP 64
#define PTS (BB*NN)      // 16384
#define NTILES (PTS/4)   // 4096 tiles of 4 points (64 rows)

// ---------------- scratch (no allocations allowed) ----------------
__device__ int   g_knn[PTS*KK];            // 1 MB
__device__ float g_q  [PTS*DM];            // 8 MB
__device__ float g_fk [PTS*DM];            // 8 MB
__device__ float g_fv [PTS*DM];            // 8 MB
__device__ float g_pos[(size_t)PTS*KK*DM]; // 128 MB
__device__ float g_res[PTS*DM];            // 8 MB

// packed fp32x2 FMA (Blackwell)
static __device__ __forceinline__ float2 ffma2(float2 a, float2 b, float2 c){
    float2 d;
    asm("fma.rn.f32x2 %0, %1, %2, %3;"
        : "=l"(reinterpret_cast<unsigned long long&>(d))
        : "l"(reinterpret_cast<unsigned long long&>(a)),
          "l"(reinterpret_cast<unsigned long long&>(b)),
          "l"(reinterpret_cast<unsigned long long&>(c)));
    return d;
}

static __device__ __forceinline__ uint32_t smem_u32(const void* p){
    uint32_t a;
    asm("{ .reg .u64 t; cvta.to.shared.u64 t, %1; cvt.u32.u64 %0, t; }" : "=r"(a) : "l"(p));
    return a;
}
static __device__ __forceinline__ void ldsm_x4(uint32_t* r, uint32_t addr){
    asm volatile("ldmatrix.sync.aligned.m8n8.x4.shared.b16 {%0,%1,%2,%3}, [%4];"
        : "=r"(r[0]), "=r"(r[1]), "=r"(r[2]), "=r"(r[3]) : "r"(addr));
}
static __device__ __forceinline__ void ldsm_x2t(uint32_t* r, uint32_t addr){
    asm volatile("ldmatrix.sync.aligned.m8n8.x2.trans.shared.b16 {%0,%1}, [%2];"
        : "=r"(r[0]), "=r"(r[1]) : "r"(addr));
}
static __device__ __forceinline__ void mma_bf16(float* c, const uint32_t* a, const uint32_t* b){
    asm volatile("mma.sync.aligned.m16n8k16.row.col.f32.bf16.bf16.f32 "
        "{%0,%1,%2,%3}, {%4,%5,%6,%7}, {%8,%9}, {%0,%1,%2,%3};"
        : "+f"(c[0]), "+f"(c[1]), "+f"(c[2]), "+f"(c[3])
        : "r"(a[0]), "r"(a[1]), "r"(a[2]), "r"(a[3]), "r"(b[0]), "r"(b[1]));
}
static __device__ __forceinline__ uint32_t pack_bf2(float lo, float hi){
    uint32_t r;
    asm("cvt.rn.bf16x2.f32 %0, %1, %2;" : "=r"(r) : "f"(hi), "f"(lo));
    return r;
}

#define LDW 136   // bf16 leading dim for activation/weight tiles

// =================================================================
// Kernel 1: kNN (unchanged, passing). grid (64,4), 256 threads.
// =================================================================
__global__ void __launch_bounds__(256, 3) knn_kernel(const float* __restrict__ xyz)
{
    extern __shared__ float4 s4[];
    int b = blockIdx.y;
    const float* xb = xyz + (size_t)b*NN*3;
    for (int m = threadIdx.x; m < NN; m += blockDim.x){
        float x = xb[m*3+0], y = xb[m*3+1], z = xb[m*3+2];
        s4[m] = make_float4(x, y, z, x*x + y*y + z*z);
    }
    __syncthreads();

    int lane = threadIdx.x & 31;
    int warp = threadIdx.x >> 5;
    int quad = lane >> 2;
    int sl   = lane & 3;
    int q    = blockIdx.x*64 + warp*8 + quad;

    float4 qp = s4[q];
    float bd[KK]; int bi[KK];
    #pragma unroll
    for (int i = 0; i < KK; i++){ bd[i] = 3.4e38f; bi[i] = 0x7fffffff; }

    #pragma unroll 4
    for (int t = 0; t < NN/4; t++){
        int m = sl + 4*t;
        float4 c = s4[m];
        float d = qp.w + c.w;
        d = fmaf(-2.0f*c.x, qp.x, d);
        d = fmaf(-2.0f*c.y, qp.y, d);
        d = fmaf(-2.0f*c.z, qp.z, d);
        if (d < bd[KK-1]){
            float cd = d; int ci = m;
            #pragma unroll
            for (int i = 0; i < KK; i++){
                bool less = cd < bd[i];
                float nd = less ? cd : bd[i];
                int   ni = less ? ci : bi[i];
                float xd = less ? bd[i] : cd;
                int   xi = less ? bi[i] : ci;
                bd[i] = nd; bi[i] = ni; cd = xd; ci = xi;
            }
        }
    }

    int* outp = g_knn + ((size_t)b*NN + q)*KK;
    #pragma unroll 1
    for (int r = 0; r < KK; r++){
        float md = bd[0]; int mi = bi[0];
        float od; int oi;
        od = __shfl_xor_sync(0xffffffffu, md, 1); oi = __shfl_xor_sync(0xffffffffu, mi, 1);
        if (od < md || (od == md && oi < mi)){ md = od; mi = oi; }
        od = __shfl_xor_sync(0xffffffffu, md, 2); oi = __shfl_xor_sync(0xffffffffu, mi, 2);
        if (od < md || (od == md && oi < mi)){ md = od; mi = oi; }
        if (mi == bi[0] && md == bd[0]){
            #pragma unroll
            for (int i = 0; i < KK-1; i++){ bd[i] = bd[i+1]; bi[i] = bi[i+1]; }
            bd[KK-1] = 3.4e38f; bi[KK-1] = 0x7fffffff;
        }
        if (sl == 0) outp[r] = mi;
    }
}

// =================================================================
// Kernel 2: f=features@Wf1+bf1; q=f@Wq; fk=f@Wk; fv=f@Wv
// (unchanged FFMA2 version from the 1251us passing round)
// =================================================================
__global__ void __launch_bounds__(512, 1) feat_kernel(
    const float* __restrict__ features,
    const float* __restrict__ Wf1, const float* __restrict__ bf1,
    const float* __restrict__ Wq,  const float* __restrict__ Wk,
    const float* __restrict__ Wv)
{
    extern __shared__ float sm2[];
    float2* sXd = (float2*)sm2;
    float2* sFd = (float2*)(sm2 + 8192);
    float*  sW  = sm2 + 24576;

    int tid  = threadIdx.x;
    int row0 = blockIdx.x * 64;
    int lane = tid & 31, warp = tid >> 5;
    int r0   = warp * 4;

    for (int i = tid; i < 64*64/2; i += 512){
        float2 v = ((const float2*)(features + (size_t)row0*DP))[i];
        ((float4*)sXd)[i] = make_float4(v.x, v.x, v.y, v.y);
    }
    for (int i = tid; i < 64*128/4; i += 512)
        ((float4*)sW)[i] = ((const float4*)Wf1)[i];
    __syncthreads();

    {
        float4 bv = *(const float4*)(bf1 + 4*lane);
        float2 a0[4], a1[4];
        #pragma unroll
        for (int r = 0; r < 4; r++){ a0[r] = make_float2(bv.x, bv.y); a1[r] = make_float2(bv.z, bv.w); }
        #pragma unroll 4
        for (int j = 0; j < 64; j += 2){
            float4 w0 = *(float4*)(sW + (j+0)*128 + 4*lane);
            float4 w1 = *(float4*)(sW + (j+1)*128 + 4*lane);
            #pragma unroll
            for (int r = 0; r < 4; r++){
                float4 xv = *(float4*)(sXd + (r0+r)*64 + j);
                a0[r] = ffma2(make_float2(xv.x,xv.y), make_float2(w0.x,w0.y), a0[r]);
                a1[r] = ffma2(make_float2(xv.x,xv.y), make_float2(w0.z,w0.w), a1[r]);
                a0[r] = ffma2(make_float2(xv.z,xv.w), make_float2(w1.x,w1.y), a0[r]);
                a1[r] = ffma2(make_float2(xv.z,xv.w), make_float2(w1.z,w1.w), a1[r]);
            }
        }
        #pragma unroll
        for (int r = 0; r < 4; r++){
            *(float4*)(sFd + (r0+r)*128 + 4*lane + 0) = make_float4(a0[r].x, a0[r].x, a0[r].y, a0[r].y);
            *(float4*)(sFd + (r0+r)*128 + 4*lane + 2) = make_float4(a1[r].x, a1[r].x, a1[r].y, a1[r].y);
        }
        __syncwarp();
    }

    const float* Ws[3] = {Wq, Wk, Wv};
    float* Gs[3];
    Gs[0] = g_q; Gs[1] = g_fk; Gs[2] = g_fv;
    for (int wsel = 0; wsel < 3; wsel++){
        __syncthreads();
        for (int i = tid; i < 128*128/4; i += 512)
            ((float4*)sW)[i] = ((const float4*)Ws[wsel])[i];
        __syncthreads();
        float2 a0[4], a1[4];
        #pragma unroll
        for (int r = 0; r < 4; r++){ a0[r] = make_float2(0.f,0.f); a1[r] = make_float2(0.f,0.f); }
        #pragma unroll 4
        for (int j = 0; j < 128; j += 2){
            float4 w0 = *(float4*)(sW + (j+0)*128 + 4*lane);
            float4 w1 = *(float4*)(sW + (j+1)*128 + 4*lane);
            #pragma unroll
            for (int r = 0; r < 4; r++){
                float4 xv = *(float4*)(sFd + (r0+r)*128 + j);
                a0[r] = ffma2(make_float2(xv.x,xv.y), make_float2(w0.x,w0.y), a0[r]);
                a1[r] = ffma2(make_float2(xv.x,xv.y), make_float2(w0.z,w0.w), a1[r]);
                a0[r] = ffma2(make_float2(xv.z,xv.w), make_float2(w1.x,w1.y), a0[r]);
                a1[r] = ffma2(make_float2(xv.z,xv.w), make_float2(w1.z,w1.w), a1[r]);
            }
        }
        float* gout = Gs[wsel];
        #pragma unroll
        for (int r = 0; r < 4; r++)
            *(float4*)(gout + (size_t)(row0 + r0 + r)*DM + 4*lane) =
                make_float4(a0[r].x, a0[r].y, a1[r].x, a1[r].y);
    }
}

// =================================================================
// Kernel 3: pos = relu(rel@Wd1+bd1)@Wd2+bd2 via HMMA (mma.sync bf16).
// Persistent 148 blocks, 256 threads, 64-row tiles.
// =================================================================
__global__ void __launch_bounds__(256, 1) pos_kernel(
    const float* __restrict__ xyz,
    const float* __restrict__ Wd1, const float* __restrict__ bd1,
    const float* __restrict__ Wd2, const float* __restrict__ bd2)
{
    extern __shared__ char smC[];
    __nv_bfloat16* sW = (__nv_bfloat16*)smC;            // [128][LDW] = 34816 B
    __nv_bfloat16* sU = (__nv_bfloat16*)(smC + 34816);  // [64][LDW]  = 17408 B
    float* sRel = (float*)(smC + 52224);                // 64*3 floats
    int*   sidx = (int*)(smC + 53248);                  // 64 ints

    int tid = threadIdx.x;
    int lane = tid & 31, warp = tid >> 5;
    int rbase = (warp & 3) * 16;
    int cbase = (warp >> 2) * 64;
    int m = lane & 3, r = lane >> 2;

    for (int idx = tid; idx < 128*128; idx += 256){
        int k = idx >> 7, n = idx & 127;
        sW[k*LDW + n] = __float2bfloat16(Wd2[idx]);
    }
    int c = tid & 127;
    float w0c = Wd1[c], w1c = Wd1[128 + c], w2c = Wd1[256 + c], b1c = bd1[c];
    float bA[8], bBv[8];
    #pragma unroll
    for (int nt = 0; nt < 8; nt++){
        int colA = cbase + nt*8 + 2*m;
        bA[nt] = bd2[colA]; bBv[nt] = bd2[colA + 1];
    }
    uint32_t aW = smem_u32(sW), aU = smem_u32(sU);
    __syncthreads();

    for (int tile = blockIdx.x; tile < NTILES; tile += gridDim.x){
        int p0 = tile * 4;
        int base = p0 & ~(NN-1);
        __syncthreads();
        if (tid < 64){
            int nb0 = g_knn[(size_t)(p0 + (tid >> 4))*KK + (tid & 15)];
            sidx[tid] = nb0;
            int p = p0 + (tid >> 4);
            int nb = base + nb0;
            sRel[tid*3+0] = xyz[(size_t)p*3+0] - xyz[(size_t)nb*3+0];
            sRel[tid*3+1] = xyz[(size_t)p*3+1] - xyz[(size_t)nb*3+1];
            sRel[tid*3+2] = xyz[(size_t)p*3+2] - xyz[(size_t)nb*3+2];
        }
        __syncthreads();

        // u = relu(rel@Wd1+bd1) -> sU bf16
        #pragma unroll
        for (int rr = tid >> 7; rr < 64; rr += 2){
            float u = b1c;
            u = fmaf(sRel[rr*3+0], w0c, u);
            u = fmaf(sRel[rr*3+1], w1c, u);
            u = fmaf(sRel[rr*3+2], w2c, u);
            sU[rr*LDW + c] = __float2bfloat16(fmaxf(u, 0.f));
        }
        __syncthreads();

        // GEMM: C = u @ Wd2
        float C[8][4];
        #pragma unroll
        for (int nt = 0; nt < 8; nt++){ C[nt][0]=0.f; C[nt][1]=0.f; C[nt][2]=0.f; C[nt][3]=0.f; }
        #pragma unroll
        for (int k = 0; k < 8; k++){
            uint32_t a[4], b[2];
            ldsm_x4(a, aU + ((rbase + (lane & 15))*LDW + k*16 + (lane >> 4)*8)*2);
            #pragma unroll
            for (int nt = 0; nt < 8; nt++){
                ldsm_x2t(b, aW + ((k*16 + (lane & 15))*LDW + cbase + nt*8)*2);
                mma_bf16(C[nt], a, b);
            }
        }
        // epilogue: g_pos = C + bd2
        float* gp = g_pos + (size_t)tile*64*DM;
        #pragma unroll
        for (int nt = 0; nt < 8; nt++){
            int colA = cbase + nt*8 + 2*m;
            *(float2*)(gp + (size_t)(rbase + r    )*DM + colA) = make_float2(C[nt][0] + bA[nt], C[nt][1] + bBv[nt]);
            *(float2*)(gp + (size_t)(rbase + r + 8)*DM + colA) = make_float2(C[nt][2] + bA[nt], C[nt][3] + bBv[nt]);
        }
    }
}

// =================================================================
// Kernel 4: attention core via HMMA. Persistent 148 blocks, 256 thr.
// t=q-fk+pos -> h=relu(t@Wg1+bg1) -> a=h@Wg2+bg2 -> softmax(k) ->
// res = sum attn*(fv+pos). Softmax via register butterflies.
// =================================================================
__global__ void __launch_bounds__(256, 1) attn_kernel(
    const float* __restrict__ Wg1, const float* __restrict__ bg1,
    const float* __restrict__ Wg2, const float* __restrict__ bg2)
{
    extern __shared__ char smD[];
    __nv_bfloat16* sW1 = (__nv_bfloat16*)smD;             // 34816
    __nv_bfloat16* sW2 = (__nv_bfloat16*)(smD + 34816);   // 34816
    __nv_bfloat16* sTa = (__nv_bfloat16*)(smD + 69632);   // 17408
    __nv_bfloat16* sTb = (__nv_bfloat16*)(smD + 87040);   // 17408
    float* sV = (float*)(smD + 104448);                   // [64][132] f32 = 33792
    int*   sidx = (int*)(smD + 138240);                   // 64 ints

    int tid = threadIdx.x;
    int lane = tid & 31, warp = tid >> 5;
    int rbase = (warp & 3) * 16;     // point within tile
    int cbase = (warp >> 2) * 64;
    int m = lane & 3, r = lane >> 2;
    const float invs = 0.08838834764831845f;   // 1/sqrt(128)

    for (int idx = tid; idx < 128*128; idx += 256){
        int k = idx >> 7, n = idx & 127;
        sW1[k*LDW + n] = __float2bfloat16(Wg1[idx]);
        sW2[k*LDW + n] = __float2bfloat16(Wg2[idx]);
    }
    float b1A[8], b1B[8], b2A[8], b2B[8];
    #pragma unroll
    for (int nt = 0; nt < 8; nt++){
        int colA = cbase + nt*8 + 2*m;
        b1A[nt] = bg1[colA]; b1B[nt] = bg1[colA + 1];
        b2A[nt] = bg2[colA]; b2B[nt] = bg2[colA + 1];
    }
    uint32_t aW1 = smem_u32(sW1), aW2 = smem_u32(sW2);
    uint32_t aTa = smem_u32(sTa), aTb = smem_u32(sTb);
    int c = tid & 127;
    __syncthreads();

    for (int tile = blockIdx.x; tile < NTILES; tile += gridDim.x){
        int p0 = tile * 4;
        int base = p0 & ~(NN-1);
        __syncthreads();
        if (tid < 64) sidx[tid] = g_knn[(size_t)(p0 + (tid >> 4))*KK + (tid & 15)];
        __syncthreads();

        // t = q - fk + pos -> sTa (bf16) ; v' = fv + pos -> sV (f32)
        #pragma unroll
        for (int rr = tid >> 7; rr < 64; rr += 2){
            int p = rr >> 4;
            int nb = base + sidx[rr];
            float pos = g_pos[((size_t)tile*64 + rr)*DM + c];
            float t = g_q[(size_t)(p0+p)*DM + c] - g_fk[(size_t)nb*DM + c] + pos;
            sTa[rr*LDW + c] = __float2bfloat16(t);
            sV[rr*132 + c] = g_fv[(size_t)nb*DM + c] + pos;
        }
        __syncthreads();

        // GEMM1: C = t @ Wg1 ; h = relu(C + bg1) -> sTb (bf16)
        float C[8][4];
        #pragma unroll
        for (int nt = 0; nt < 8; nt++){ C[nt][0]=0.f; C[nt][1]=0.f; C[nt][2]=0.f; C[nt][3]=0.f; }
        #pragma unroll
        for (int k = 0; k < 8; k++){
            uint32_t a[4], b[2];
            ldsm_x4(a, aTa + ((rbase + (lane & 15))*LDW + k*16 + (lane >> 4)*8)*2);
            #pragma unroll
            for (int nt = 0; nt < 8; nt++){
                ldsm_x2t(b, aW1 + ((k*16 + (lane & 15))*LDW + cbase + nt*8)*2);
                mma_bf16(C[nt], a, b);
            }
        }
        #pragma unroll
        for (int nt = 0; nt < 8; nt++){
            int colA = cbase + nt*8 + 2*m;
            float h0 = fmaxf(C[nt][0] + b1A[nt], 0.f), h1 = fmaxf(C[nt][1] + b1B[nt], 0.f);
            float h2 = fmaxf(C[nt][2] + b1A[nt], 0.f), h3 = fmaxf(C[nt][3] + b1B[nt], 0.f);
            *(uint32_t*)(sTb + (rbase + r    )*LDW + colA) = pack_bf2(h0, h1);
            *(uint32_t*)(sTb + (rbase + r + 8)*LDW + colA) = pack_bf2(h2, h3);
        }
        __syncthreads();

        // GEMM2: C = h @ Wg2
        #pragma unroll
        for (int nt = 0; nt < 8; nt++){ C[nt][0]=0.f; C[nt][1]=0.f; C[nt][2]=0.f; C[nt][3]=0.f; }
        #pragma unroll
        for (int k = 0; k < 8; k++){
            uint32_t a[4], b[2];
            ldsm_x4(a, aTb + ((rbase + (lane & 15))*LDW + k*16 + (lane >> 4)*8)*2);
            #pragma unroll
            for (int nt = 0; nt < 8; nt++){
                ldsm_x2t(b, aW2 + ((k*16 + (lane & 15))*LDW + cbase + nt*8)*2);
                mma_bf16(C[nt], a, b);
            }
        }

        // softmax over k (warp rows = this point's 16 neighbors) + weighted sum
        float* gr = g_res + (size_t)(p0 + (warp & 3))*DM;
        #pragma unroll
        for (int nt = 0; nt < 8; nt++){
            int colA = cbase + nt*8 + 2*m;
            float aA0 = C[nt][0] + b2A[nt], aB0 = C[nt][1] + b2B[nt];   // k = r
            float aA1 = C[nt][2] + b2A[nt], aB1 = C[nt][3] + b2B[nt];   // k = r+8
            float mA = fmaxf(aA0, aA1), mB = fmaxf(aB0, aB1);
            #pragma unroll
            for (int d = 4; d <= 16; d <<= 1){
                mA = fmaxf(mA, __shfl_xor_sync(0xffffffffu, mA, d));
                mB = fmaxf(mB, __shfl_xor_sync(0xffffffffu, mB, d));
            }
            float yA0 = __expf((aA0 - mA)*invs), yA1 = __expf((aA1 - mA)*invs);
            float yB0 = __expf((aB0 - mB)*invs), yB1 = __expf((aB1 - mB)*invs);
            float sA = yA0 + yA1, sB = yB0 + yB1;
            float vA0 = sV[(rbase + r)*132 + colA], vA1 = sV[(rbase + r + 8)*132 + colA];
            float vB0 = sV[(rbase + r)*132 + colA + 1], vB1 = sV[(rbase + r + 8)*132 + colA + 1];
            float rA = yA0*vA0 + yA1*vA1, rB = yB0*vB0 + yB1*vB1;
            #pragma unroll
            for (int d = 4; d <= 16; d <<= 1){
                sA += __shfl_xor_sync(0xffffffffu, sA, d);
                sB += __shfl_xor_sync(0xffffffffu, sB, d);
                rA += __shfl_xor_sync(0xffffffffu, rA, d);
                rB += __shfl_xor_sync(0xffffffffu, rB, d);
            }
            if (r == 0)
                *(float2*)(gr + colA) = make_float2(rA / sA, rB / sB);
        }
    }
}

// =================================================================
// Kernel 5: out = res@Wo + bo + shortcut (unchanged).
// =================================================================
__global__ void __launch_bounds__(256, 2) out_kernel(
    const float* __restrict__ features,
    const float* __restrict__ Wo, const float* __restrict__ bo,
    float* __restrict__ out)
{
    extern __shared__ float smE[];
    float2* sRd = (float2*)smE;
    float*  sWo = smE + 16384;
    int tid = threadIdx.x;
    int row0 = blockIdx.x * 64;
    int lane = tid & 31, warp = tid >> 5;
    int r0 = warp * 8;

    for (int i = tid; i < 64*128/2; i += 256){
        float2 v = ((const float2*)(g_res + (size_t)row0*DM))[i];
        ((float4*)sRd)[i] = make_float4(v.x, v.x, v.y, v.y);
    }
    for (int i = tid; i < 8192/4; i += 256)
        ((float4*)sWo)[i] = ((const float4*)Wo)[i];
    __syncthreads();

    float2 acc[8];
    float2 bias = *(const float2*)(bo + 2*lane);
    #pragma unroll
    for (int r = 0; r < 8; r++) acc[r] = bias;
    #pragma unroll 4
    for (int j = 0; j < 128; j += 2){
        float2 w0 = *(float2*)(sWo + (j+0)*64 + 2*lane);
        float2 w1 = *(float2*)(sWo + (j+1)*64 + 2*lane);
        #pragma unroll
        for (int r = 0; r < 8; r++){
            float4 xv = *(float4*)(sRd + (r0+r)*128 + j);
            acc[r] = ffma2(make_float2(xv.x,xv.y), w0, acc[r]);
            acc[r] = ffma2(make_float2(xv.z,xv.w), w1, acc[r]);
        }
    }
    #pragma unroll
    for (int r = 0; r < 8; r++){
        int p = row0 + r0 + r;
        float2 sc = *(const float2*)(features + (size_t)p*DP + 2*lane);
        *(float2*)(out + (size_t)p*DP + 2*lane) = make_float2(acc[r].x + sc.x, acc[r].y + sc.y);
    }
}

// =================================================================
extern "C" void kernel_launch(void* const* d_in, const int* in_sizes, int n_in,
                              void* d_out, int out_size)
{
    const float* xyz      = (const float*)d_in[0];
    const float* features = (const float*)d_in[1];
    const float* Wd1 = (const float*)d_in[2];  const float* bd1 = (const float*)d_in[3];
    const float* Wd2 = (const float*)d_in[4];  const float* bd2 = (const float*)d_in[5];
    const float* Wf1 = (const float*)d_in[6];  const float* bf1 = (const float*)d_in[7];
    const float* Wq  = (const float*)d_in[8];
    const float* Wk  = (const float*)d_in[9];
    const float* Wv  = (const float*)d_in[10];
    const float* Wg1 = (const float*)d_in[11]; const float* bg1 = (const float*)d_in[12];
    const float* Wg2 = (const float*)d_in[13]; const float* bg2 = (const float*)d_in[14];
    const float* Wo  = (const float*)d_in[15]; const float* bo  = (const float*)d_in[16];
    float* out = (float*)d_out;

    cudaFuncSetAttribute(knn_kernel,  cudaFuncAttributeMaxDynamicSharedMemorySize, 65536);
    cudaFuncSetAttribute(feat_kernel, cudaFuncAttributeMaxDynamicSharedMemorySize, 163840);
    cudaFuncSetAttribute(pos_kernel,  cudaFuncAttributeMaxDynamicSharedMemorySize, 53504);
    cudaFuncSetAttribute(attn_kernel, cudaFuncAttributeMaxDynamicSharedMemorySize, 138496);
    cudaFuncSetAttribute(out_kernel,  cudaFuncAttributeMaxDynamicSharedMemorySize, 98304);

    knn_kernel <<<dim3(64, 4), 256, 65536 >>>(xyz);
    feat_kernel<<<PTS/64, 512, 163840>>>(features, Wf1, bf1, Wq, Wk, Wv);
    pos_kernel <<<148, 256, 53504>>>(xyz, Wd1, bd1, Wd2, bd2);
    attn_kernel<<<148, 256, 138496>>>(Wg1, bg1, Wg2, bg2);
    out_kernel <<<PTS/64, 256, 98304>>>(features, Wo, bo, out);
}